// round 13
// baseline (speedup 1.0000x reference)
#include <cuda_runtime.h>
#include <math.h>

#define NRAYS 16384
#define MAXS 128

// ---------------- scratch (device globals; no allocation allowed) ----------
__device__ float g_dirs[NRAYS * 3];
__device__ float g_dbuf[2][NRAYS * MAXS];
__device__ float g_sbuf[2][NRAYS * MAXS];
__device__ float g_dfine[NRAYS * 16];
__device__ float g_sdff[NRAYS * 16];

// ---------------- math helpers ---------------------------------------------
__device__ __forceinline__ float softplus_fast(float x) {
    float t = __expf(-fabsf(x));
    return fmaxf(x, 0.0f) + __logf(1.0f + t);
}
__device__ __forceinline__ float sigmoid_fast(float x) {
    return __fdividef(1.0f, 1.0f + __expf(-x));
}
__device__ __forceinline__ float sigmoid_precise(float x) {
    return 1.0f / (1.0f + expf(-x));
}

// ---------------- tf32 helpers ----------------------------------------------
__device__ __forceinline__ unsigned tf32_of(float x) {
    unsigned r;
    asm("cvt.rna.tf32.f32 %0, %1;" : "=r"(r) : "f"(x));
    return r;
}
__device__ __forceinline__ void mma_tf32(float* c, const unsigned* a, const unsigned* b) {
    asm volatile(
        "mma.sync.aligned.m16n8k8.row.col.f32.tf32.tf32.f32 "
        "{%0,%1,%2,%3}, {%4,%5,%6,%7}, {%8,%9}, {%0,%1,%2,%3};"
        : "+f"(c[0]), "+f"(c[1]), "+f"(c[2]), "+f"(c[3])
        : "r"(a[0]), "r"(a[1]), "r"(a[2]), "r"(a[3]), "r"(b[0]), "r"(b[1]));
}

// ---------------- init: normalize dirs, fill coarse d ----------------------
__global__ void init_kernel(const float* __restrict__ rd,
                            const float* __restrict__ nearp,
                            const float* __restrict__ farp) {
    int r = blockIdx.x * blockDim.x + threadIdx.x;
    if (r >= NRAYS) return;
    float dx = rd[r * 3 + 0], dy = rd[r * 3 + 1], dz = rd[r * 3 + 2];
    float nrm = sqrtf(dx * dx + dy * dy + dz * dz);
    dx /= nrm; dy /= nrm; dz /= nrm;
    g_dirs[r * 3 + 0] = dx; g_dirs[r * 3 + 1] = dy; g_dirs[r * 3 + 2] = dz;
    float nr = nearp[r], fr = farp[r];
    for (int j = 0; j < 64; j++) {
        float t = (float)j / 63.0f;
        g_dbuf[0][r * MAXS + j] = nr * (1.0f - t) + fr * t;
    }
}

// ---------------- SDF MLP: 128 pts/CTA, tensor-core layer-2 (3xTF32) --------
// tf32 hi/lo pre-split in SMEM; MMA loop = LDS + HMMA only.
// smem (floats):
//   [0,4352)        w2q_hi [q][k] pitch 68
//   [4352,8704)     w2q_lo
//   [8704,17152)    hsh_hi [k][pt] pitch 132
//   [17152,25600)   hsh_lo
//   [25600,26112)   partial [mg=4][pt=128]
//   [26112,26304)   w1s
//   [26304,26368)   b1s
//   [26368,26432)   b2s
//   [26432,26496)   w3s
//   [26496,26624)   pnorm
//   [26624]         b3s
#define WP 68
#define HP 132
#define SDF_SMEM_FLOATS 26625
__global__ void __launch_bounds__(256)
sdf_kernel(const float* __restrict__ o,
           const float* __restrict__ w1, const float* __restrict__ b1,
           const float* __restrict__ w2, const float* __restrict__ b2,
           const float* __restrict__ w3, const float* __restrict__ b3,
           int mode) {
    extern __shared__ __align__(16) float sm[];
    float* w2q_hi = sm;
    float* w2q_lo = sm + 4352;
    float* hsh_hi = sm + 8704;
    float* hsh_lo = sm + 17152;
    float* partial= sm + 25600;
    float* w1s    = sm + 26112;
    float* b1s    = sm + 26304;
    float* b2s    = sm + 26368;
    float* w3s    = sm + 26432;
    float* pnorm  = sm + 26496;
    float* b3s    = sm + 26624;

    int tid = threadIdx.x;
    // transpose + split w2 [k][q] -> w2q_{hi,lo} [q][k] pitch 68
    for (int i = tid; i < 4096; i += 256) {
        float v = w2[i];
        unsigned hi = tf32_of(v);
        float lo = v - __uint_as_float(hi);
        int idx = (i & 63) * WP + (i >> 6);
        w2q_hi[idx] = __uint_as_float(hi);
        w2q_lo[idx] = __uint_as_float(tf32_of(lo));
    }
    if (tid < 192) w1s[tid] = w1[tid];
    if (tid < 64) { b1s[tid] = b1[tid]; b2s[tid] = b2[tid]; w3s[tid] = w3[tid]; }
    if (tid == 0) b3s[0] = b3[0];
    __syncthreads();

    const float* dvals = mode ? g_dfine : g_dbuf[0];
    float* outp        = mode ? g_sdff  : g_sbuf[0];
    int spr    = mode ? 16 : 64;
    int stride = mode ? 16 : MAXS;

    // ---- layer 1: 256 threads = 128 pts x 2 k-groups of 32; split to smem --
    {
        int pt = tid & 127, kg = tid >> 7;
        int gp = blockIdx.x * 128 + pt;
        int ray = gp / spr;
        int j   = gp - ray * spr;
        float dv = dvals[ray * stride + j];
        float ox = o[ray * 3 + 0], oy = o[ray * 3 + 1], oz = o[ray * 3 + 2];
        float dx = g_dirs[ray * 3 + 0], dy = g_dirs[ray * 3 + 1], dz = g_dirs[ray * 3 + 2];
        float px = fmaf(dv, dx, ox), py = fmaf(dv, dy, oy), pz = fmaf(dv, dz, oz);
        if (kg == 0)
            pnorm[pt] = sqrtf(fmaf(px, px, fmaf(py, py, pz * pz)));
        int k0 = kg * 32;
#pragma unroll
        for (int k = k0; k < k0 + 32; k++) {
            float a = b1s[k];
            a = fmaf(px, w1s[k], a);
            a = fmaf(py, w1s[64 + k], a);
            a = fmaf(pz, w1s[128 + k], a);
            float h = softplus_fast(a);
            unsigned hi = tf32_of(h);
            float lo = h - __uint_as_float(hi);
            hsh_hi[k * HP + pt] = __uint_as_float(hi);
            hsh_lo[k * HP + pt] = __uint_as_float(tf32_of(lo));
        }
    }
    __syncthreads();

    // ---- layer 2: tensor cores. D[q][pt] = W2T[q][k] @ H[k][pt] ----
    // 8 warps = 4 q-tiles(16) x 2 pt-halves(64). m16n8k8, 3xTF32, pre-split.
    {
        int wid  = tid >> 5;
        int lane = tid & 31;
        int g = lane >> 2;          // group 0..7
        int t = lane & 3;           // thread-in-group
        int mq  = (wid & 3) * 16;   // q-tile base
        int np0 = (wid >> 2) * 64;  // pt-half base

        float c[8][4];
#pragma unroll
        for (int nt = 0; nt < 8; nt++)
#pragma unroll
            for (int i = 0; i < 4; i++) c[nt][i] = 0.0f;

#pragma unroll
        for (int ks = 0; ks < 8; ks++) {
            int kb = ks * 8;
            int a00 = (mq + g) * WP + kb + t;
            int a10 = (mq + g + 8) * WP + kb + t;
            unsigned ahi[4], alo[4];
            ahi[0] = __float_as_uint(w2q_hi[a00]);
            ahi[1] = __float_as_uint(w2q_hi[a10]);
            ahi[2] = __float_as_uint(w2q_hi[a00 + 4]);
            ahi[3] = __float_as_uint(w2q_hi[a10 + 4]);
            alo[0] = __float_as_uint(w2q_lo[a00]);
            alo[1] = __float_as_uint(w2q_lo[a10]);
            alo[2] = __float_as_uint(w2q_lo[a00 + 4]);
            alo[3] = __float_as_uint(w2q_lo[a10 + 4]);
#pragma unroll
            for (int nt = 0; nt < 8; nt++) {
                int pt0 = np0 + nt * 8;
                int b0 = (kb + t) * HP + pt0 + g;
                int b1i = (kb + t + 4) * HP + pt0 + g;
                unsigned bhi[2], blo[2];
                bhi[0] = __float_as_uint(hsh_hi[b0]);
                bhi[1] = __float_as_uint(hsh_hi[b1i]);
                blo[0] = __float_as_uint(hsh_lo[b0]);
                blo[1] = __float_as_uint(hsh_lo[b1i]);
                mma_tf32(c[nt], ahi, bhi);
                mma_tf32(c[nt], ahi, blo);
                mma_tf32(c[nt], alo, bhi);
            }
        }

        // epilogue: softplus + layer3, reduce over 8 groups via shfl
        int q_lo = mq + g, q_hi = mq + g + 8;
        float bql = b2s[q_lo], bqh = b2s[q_hi];
        float wql = w3s[q_lo], wqh = w3s[q_hi];
#pragma unroll
        for (int nt = 0; nt < 8; nt++) {
            int pt0 = np0 + nt * 8;
            float s0 = fmaf(softplus_fast(c[nt][0] + bql), wql,
                            softplus_fast(c[nt][2] + bqh) * wqh);
            float s1 = fmaf(softplus_fast(c[nt][1] + bql), wql,
                            softplus_fast(c[nt][3] + bqh) * wqh);
#pragma unroll
            for (int mask = 4; mask <= 16; mask <<= 1) {
                s0 += __shfl_xor_sync(0xffffffffu, s0, mask);
                s1 += __shfl_xor_sync(0xffffffffu, s1, mask);
            }
            if (g == 0) {
                partial[(wid & 3) * 128 + pt0 + 2 * t]     = s0;
                partial[(wid & 3) * 128 + pt0 + 2 * t + 1] = s1;
            }
        }
    }
    __syncthreads();

    // ---- final reduce + write: 128 threads, one per point ----
    if (tid < 128) {
        float s = partial[tid] + partial[128 + tid] +
                  partial[256 + tid] + partial[384 + tid];
        int gp = blockIdx.x * 128 + tid;
        int ray = gp / spr;
        int j   = gp - ray * spr;
        outp[ray * stride + j] = pnorm[tid] - 0.8f + 0.1f * (b3s[0] + s);
    }
}

// ---------------- upsample: one warp per ray --------------------------------
#define UP_PAD 116
__global__ void upsample_kernel(int n, float s_i, int pp) {
    int gwarp = (blockIdx.x * blockDim.x + threadIdx.x) >> 5;
    int lane  = threadIdx.x & 31;
    int wib   = (threadIdx.x >> 5);
    __shared__ float scdf[8 * UP_PAD];
    if (gwarp >= NRAYS) return;

    const float* d  = g_dbuf[pp] + gwarp * MAXS;
    const float* sd = g_sbuf[pp] + gwarp * MAXS;
    int m = n - 1;
    int base = lane * 4;

    float dj[5], sj[5];
#pragma unroll
    for (int i = 0; i < 5; i++) {
        int idx = base + i;
        bool v = idx < n;
        dj[i] = v ? d[idx] : 1.0f;
        sj[i] = v ? sd[idx] : 0.0f;
    }

    float raw[4];
#pragma unroll
    for (int i = 0; i < 4; i++)
        raw[i] = (sj[i + 1] - sj[i]) / (dj[i + 1] - dj[i] + 1e-5f);

    float prevr = __shfl_up_sync(0xffffffffu, raw[3], 1);
    if (lane == 0) prevr = 0.0f;

    float alpha[4];
#pragma unroll
    for (int i = 0; i < 4; i++) {
        float dvv = fminf(prevr, raw[i]);
        prevr = raw[i];
        dvv = fminf(fmaxf(dvv, -10.0f), 0.0f);
        float mid  = 0.5f * (sj[i] + sj[i + 1]);
        float dist = dj[i + 1] - dj[i];
        float pe = mid - dvv * dist * 0.5f;
        float ne = mid + dvv * dist * 0.5f;
        float pc = sigmoid_precise(pe * s_i);
        float nc = sigmoid_precise(ne * s_i);
        alpha[i] = (pc - nc + 1e-5f) / (pc + 1e-5f);
    }

    float Tloc[4], pl = 1.0f;
#pragma unroll
    for (int i = 0; i < 4; i++) {
        Tloc[i] = pl;
        float om = (base + i < m) ? (1.0f - alpha[i] + 1e-10f) : 1.0f;
        pl *= om;
    }
    float v = pl;
#pragma unroll
    for (int off = 1; off < 32; off <<= 1) {
        float t = __shfl_up_sync(0xffffffffu, v, off);
        if (lane >= off) v *= t;
    }
    float exp_ = __shfl_up_sync(0xffffffffu, v, 1);
    if (lane == 0) exp_ = 1.0f;

    float wp[4], sl = 0.0f, sloc[4];
#pragma unroll
    for (int i = 0; i < 4; i++) {
        float T = exp_ * Tloc[i];
        wp[i] = (base + i < m) ? fmaf(alpha[i], T, 1e-5f) : 0.0f;
        sl += wp[i];
        sloc[i] = sl;
    }
    float tot = sl;
#pragma unroll
    for (int off = 16; off > 0; off >>= 1)
        tot += __shfl_xor_sync(0xffffffffu, tot, off);
    float vs = sl;
#pragma unroll
    for (int off = 1; off < 32; off <<= 1) {
        float t = __shfl_up_sync(0xffffffffu, vs, off);
        if (lane >= off) vs += t;
    }
    float exs = __shfl_up_sync(0xffffffffu, vs, 1);
    if (lane == 0) exs = 0.0f;

    float inv = 1.0f / tot;
    float* cdf = scdf + wib * UP_PAD;
    if (lane == 0) cdf[0] = 0.0f;
#pragma unroll
    for (int i = 0; i < 4; i++) {
        int j = base + i;
        if (j < m) cdf[j + 1] = (exs + sloc[i]) * inv;
    }
    __syncwarp();

    if (lane < 16) {
        float u = (float)lane / 15.0f;
        int lo = 0, hi = n;
        while (lo < hi) {
            int mm = (lo + hi) >> 1;
            if (cdf[mm] <= u) lo = mm + 1; else hi = mm;
        }
        int below = lo - 1;
        if (below < 0) below = 0;
        if (below > n - 1) below = n - 1;
        int above = lo;
        if (above > n - 1) above = n - 1;
        float cb = cdf[below], ca = cdf[above];
        float bb = d[below],   ba = d[above];
        float den = ca - cb;
        if (den < 1e-5f) den = 1.0f;
        float t = (u - cb) / den;
        g_dfine[gwarp * 16 + lane] = bb + t * (ba - bb);
    }
}

// ---------------- parallel stable merge (rank & scatter), ping-pong ---------
__global__ void merge_kernel(int n, int pp) {
    int gwarp = (blockIdx.x * blockDim.x + threadIdx.x) >> 5;
    int lane  = threadIdx.x & 31;
    if (gwarp >= NRAYS) return;
    const float* d  = g_dbuf[pp] + gwarp * MAXS;
    const float* sd = g_sbuf[pp] + gwarp * MAXS;
    float* dd = g_dbuf[pp ^ 1] + gwarp * MAXS;
    float* ds = g_sbuf[pp ^ 1] + gwarp * MAXS;
    const float* fd = g_dfine + gwarp * 16;
    const float* fs = g_sdff  + gwarp * 16;

    if (lane < 16) {
        float v = fd[lane];
        int lo = 0, hi = n;                // count old <= v
        while (lo < hi) { int mm = (lo + hi) >> 1; if (d[mm] <= v) lo = mm + 1; else hi = mm; }
        dd[lo + lane] = v;
        ds[lo + lane] = fs[lane];
    }
    for (int a = lane; a < n; a += 32) {
        float v = d[a];
        int lo = 0, hi = 16;               // count new < v
        while (lo < hi) { int mm = (lo + hi) >> 1; if (fd[mm] < v) lo = mm + 1; else hi = mm; }
        dd[a + lo] = v;
        ds[a + lo] = sd[a];
    }
}

// ---------------- final render: compositing + radiance MLP ------------------
__global__ void render_kernel(const float* __restrict__ o,
                              const float* __restrict__ sp,
                              const float* __restrict__ w1, const float* __restrict__ b1,
                              const float* __restrict__ w2, const float* __restrict__ b2,
                              float* __restrict__ out) {
    int r = blockIdx.x;
    int tid = threadIdx.x;
    __shared__ float dsh[128], cdfsh[128], alphash[128], scan[128];
    __shared__ float w1s[384], b1s[64], w2s[192], b2s[3];
    __shared__ float red0[128], red1[128], red2[128];

    for (int i = tid; i < 384; i += 128) w1s[i] = w1[i];
    for (int i = tid; i < 192; i += 128) w2s[i] = w2[i];
    if (tid < 64) b1s[tid] = b1[tid];
    if (tid < 3)  b2s[tid] = b2[tid];

    float s = sp[0];
    float dv = g_dbuf[0][r * MAXS + tid];
    dsh[tid] = dv;
    cdfsh[tid] = sigmoid_precise(g_sbuf[0][r * MAXS + tid] * s);
    __syncthreads();

    float a = 0.0f;
    if (tid < 127)
        a = fmaxf((cdfsh[tid] - cdfsh[tid + 1]) / (cdfsh[tid] + 1e-10f), 0.0f);
    alphash[tid] = a;
    __syncthreads();
    scan[tid] = (tid == 0) ? 1.0f : (1.0f - alphash[tid - 1] + 1e-10f);
    __syncthreads();
#pragma unroll
    for (int off = 1; off < 128; off <<= 1) {
        float t = (tid >= off) ? scan[tid - off] : 1.0f;
        __syncthreads();
        scan[tid] *= t;
        __syncthreads();
    }

    float rr = 0.f, gg = 0.f, bb = 0.f;
    if (tid < 127) {
        float vw = alphash[tid] * scan[tid];
        float dm = 0.5f * (dsh[tid] + dsh[tid + 1]);
        float ox = o[r * 3 + 0], oy = o[r * 3 + 1], oz = o[r * 3 + 2];
        float dx = g_dirs[r * 3 + 0], dy = g_dirs[r * 3 + 1], dz = g_dirs[r * 3 + 2];
        float x0 = fmaf(dm, dx, ox), x1 = fmaf(dm, dy, oy), x2 = fmaf(dm, dz, oz);
        float a0 = b2s[0], a1 = b2s[1], a2 = b2s[2];
#pragma unroll 8
        for (int j = 0; j < 64; j++) {
            float h = b1s[j];
            h = fmaf(x0, w1s[j], h);
            h = fmaf(x1, w1s[64 + j], h);
            h = fmaf(x2, w1s[128 + j], h);
            h = fmaf(dx, w1s[192 + j], h);
            h = fmaf(dy, w1s[256 + j], h);
            h = fmaf(dz, w1s[320 + j], h);
            h = softplus_fast(h);
            a0 = fmaf(h, w2s[j * 3 + 0], a0);
            a1 = fmaf(h, w2s[j * 3 + 1], a1);
            a2 = fmaf(h, w2s[j * 3 + 2], a2);
        }
        rr = sigmoid_fast(a0) * vw;
        gg = sigmoid_fast(a1) * vw;
        bb = sigmoid_fast(a2) * vw;
    }
    red0[tid] = rr; red1[tid] = gg; red2[tid] = bb;
    __syncthreads();
    for (int off = 64; off > 0; off >>= 1) {
        if (tid < off) {
            red0[tid] += red0[tid + off];
            red1[tid] += red1[tid + off];
            red2[tid] += red2[tid + off];
        }
        __syncthreads();
    }
    if (tid < 3) {
        float v = (tid == 0) ? red0[0] : (tid == 1) ? red1[0] : red2[0];
        out[r * 3 + tid] = v;
    }
}

// ---------------- launch ----------------------------------------------------
extern "C" void kernel_launch(void* const* d_in, const int* in_sizes, int n_in,
                              void* d_out, int out_size) {
    const float* rays_o = (const float*)d_in[0];
    const float* rays_d = (const float*)d_in[1];
    const float* nearp  = (const float*)d_in[2];
    const float* farp   = (const float*)d_in[3];
    const float* s_ptr  = (const float*)d_in[4];
    const float* sw1 = (const float*)d_in[5];
    const float* sb1 = (const float*)d_in[6];
    const float* sw2 = (const float*)d_in[7];
    const float* sb2 = (const float*)d_in[8];
    const float* sw3 = (const float*)d_in[9];
    const float* sb3 = (const float*)d_in[10];
    const float* rw1 = (const float*)d_in[11];
    const float* rb1 = (const float*)d_in[12];
    const float* rw2 = (const float*)d_in[13];
    const float* rb2 = (const float*)d_in[14];
    float* out = (float*)d_out;

    const int sdf_smem = SDF_SMEM_FLOATS * 4;
    cudaFuncSetAttribute(sdf_kernel,
                         cudaFuncAttributeMaxDynamicSharedMemorySize, sdf_smem);

    init_kernel<<<(NRAYS + 255) / 256, 256>>>(rays_d, nearp, farp);

    int cta_coarse = NRAYS * 64 / 128;   // 128 pts per CTA
    sdf_kernel<<<cta_coarse, 256, sdf_smem>>>(
        rays_o, sw1, sb1, sw2, sb2, sw3, sb3, 0);

    int cta_fine = NRAYS * 16 / 128;
    int warps_grid = (NRAYS * 32 + 255) / 256;   // one warp per ray
    int pp = 0;
    for (int i = 0; i < 4; i++) {
        int n = 64 + 16 * i;
        float si = 64.0f * (float)(1 << i);
        upsample_kernel<<<warps_grid, 256>>>(n, si, pp);
        sdf_kernel<<<cta_fine, 256, sdf_smem>>>(
            rays_o, sw1, sb1, sw2, sb2, sw3, sb3, 1);
        merge_kernel<<<warps_grid, 256>>>(n, pp);
        pp ^= 1;
    }
    // after 4 flips pp == 0: final data in buffer 0
    render_kernel<<<NRAYS, 128>>>(rays_o, s_ptr, rw1, rb1, rw2, rb2, out);
}

// round 14
// speedup vs baseline: 1.1810x; 1.1810x over previous
#include <cuda_runtime.h>
#include <cuda_fp16.h>
#include <math.h>

#define NRAYS 16384
#define MAXS 128

// ---------------- scratch (device globals; no allocation allowed) ----------
__device__ float g_dirs[NRAYS * 3];
__device__ float g_dbuf[2][NRAYS * MAXS];
__device__ float g_sbuf[2][NRAYS * MAXS];
__device__ float g_dfine[NRAYS * 16];
__device__ float g_sdff[NRAYS * 16];

// ---------------- math helpers ---------------------------------------------
__device__ __forceinline__ float softplus_fast(float x) {
    float t = __expf(-fabsf(x));
    return fmaxf(x, 0.0f) + __logf(1.0f + t);
}
__device__ __forceinline__ float sigmoid_fast(float x) {
    return __fdividef(1.0f, 1.0f + __expf(-x));
}
__device__ __forceinline__ float sigmoid_precise(float x) {
    return 1.0f / (1.0f + expf(-x));
}

// ---------------- fp16 split helpers (Markidis) ------------------------------
// x = hi + lo, hi/lo fp16; pack two consecutive-k values per 32-bit word.
__device__ __forceinline__ void h2split(float a, float b, unsigned& hi, unsigned& lo) {
    __half2 h = __floats2half2_rn(a, b);
    float2 hf = __half22float2(h);
    __half2 l = __floats2half2_rn(a - hf.x, b - hf.y);
    hi = *(unsigned*)&h;
    lo = *(unsigned*)&l;
}
__device__ __forceinline__ void mma_f16(float* c, const unsigned* a, const unsigned* b) {
    asm volatile(
        "mma.sync.aligned.m16n8k16.row.col.f32.f16.f16.f32 "
        "{%0,%1,%2,%3}, {%4,%5,%6,%7}, {%8,%9}, {%0,%1,%2,%3};"
        : "+f"(c[0]), "+f"(c[1]), "+f"(c[2]), "+f"(c[3])
        : "r"(a[0]), "r"(a[1]), "r"(a[2]), "r"(a[3]), "r"(b[0]), "r"(b[1]));
}

// ---------------- init: normalize dirs, fill coarse d ----------------------
__global__ void init_kernel(const float* __restrict__ rd,
                            const float* __restrict__ nearp,
                            const float* __restrict__ farp) {
    int r = blockIdx.x * blockDim.x + threadIdx.x;
    if (r >= NRAYS) return;
    float dx = rd[r * 3 + 0], dy = rd[r * 3 + 1], dz = rd[r * 3 + 2];
    float nrm = sqrtf(dx * dx + dy * dy + dz * dz);
    dx /= nrm; dy /= nrm; dz /= nrm;
    g_dirs[r * 3 + 0] = dx; g_dirs[r * 3 + 1] = dy; g_dirs[r * 3 + 2] = dz;
    float nr = nearp[r], fr = farp[r];
    for (int j = 0; j < 64; j++) {
        float t = (float)j / 63.0f;
        g_dbuf[0][r * MAXS + j] = nr * (1.0f - t) + fr * t;
    }
}

// ---------------- SDF MLP: 128 pts/CTA, fp16-split tensor layer-2 -----------
// smem (32-bit words):
//   [0,2304)       wh_hi [q][k2] pitch 36 (half2: k pair per word)
//   [2304,4608)    wh_lo
//   [4608,8832)    hh_hi [k2][pt] pitch 132
//   [8832,13056)   hh_lo
//   [13056,13568)  partial [mg=4][pt=128]  (float)
//   [13568,13760)  w1s
//   [13760,13824)  b1s
//   [13824,13888)  b2s
//   [13888,13952)  w3s
//   [13952,14080)  pnorm
//   [14080]        b3s
#define WPH 36
#define HPH 132
#define SDF_SMEM_WORDS 14081
__global__ void __launch_bounds__(256, 4)
sdf_kernel(const float* __restrict__ o,
           const float* __restrict__ w1, const float* __restrict__ b1,
           const float* __restrict__ w2, const float* __restrict__ b2,
           const float* __restrict__ w3, const float* __restrict__ b3,
           int mode) {
    extern __shared__ __align__(16) unsigned smw[];
    unsigned* wh_hi = smw;
    unsigned* wh_lo = smw + 2304;
    unsigned* hh_hi = smw + 4608;
    unsigned* hh_lo = smw + 8832;
    float* partial  = (float*)(smw + 13056);
    float* w1s      = (float*)(smw + 13568);
    float* b1s      = (float*)(smw + 13760);
    float* b2s      = (float*)(smw + 13824);
    float* w3s      = (float*)(smw + 13888);
    float* pnorm    = (float*)(smw + 13952);
    float* b3s      = (float*)(smw + 14080);

    int tid = threadIdx.x;
    // transpose + fp16-split w2 [k][q] -> wh_{hi,lo}[q][k2] (k pairs packed)
    for (int i = tid; i < 2048; i += 256) {
        int q = i >> 5, k2 = i & 31;
        float va = w2[(2 * k2) * 64 + q];
        float vb = w2[(2 * k2 + 1) * 64 + q];
        unsigned hi, lo;
        h2split(va, vb, hi, lo);
        wh_hi[q * WPH + k2] = hi;
        wh_lo[q * WPH + k2] = lo;
    }
    if (tid < 192) w1s[tid] = w1[tid];
    if (tid < 64) { b1s[tid] = b1[tid]; b2s[tid] = b2[tid]; w3s[tid] = w3[tid]; }
    if (tid == 0) b3s[0] = b3[0];
    __syncthreads();

    const float* dvals = mode ? g_dfine : g_dbuf[0];
    float* outp        = mode ? g_sdff  : g_sbuf[0];
    int spr    = mode ? 16 : 64;
    int stride = mode ? 16 : MAXS;

    // ---- layer 1: 256 threads = 128 pts x 2 k-groups of 32; split to smem --
    {
        int pt = tid & 127, kg = tid >> 7;
        int gp = blockIdx.x * 128 + pt;
        int ray = gp / spr;
        int j   = gp - ray * spr;
        float dv = dvals[ray * stride + j];
        float ox = o[ray * 3 + 0], oy = o[ray * 3 + 1], oz = o[ray * 3 + 2];
        float dx = g_dirs[ray * 3 + 0], dy = g_dirs[ray * 3 + 1], dz = g_dirs[ray * 3 + 2];
        float px = fmaf(dv, dx, ox), py = fmaf(dv, dy, oy), pz = fmaf(dv, dz, oz);
        if (kg == 0)
            pnorm[pt] = sqrtf(fmaf(px, px, fmaf(py, py, pz * pz)));
        int k20 = kg * 16;
#pragma unroll
        for (int k2 = k20; k2 < k20 + 16; k2++) {
            int k = 2 * k2;
            float a0 = b1s[k];
            a0 = fmaf(px, w1s[k], a0);
            a0 = fmaf(py, w1s[64 + k], a0);
            a0 = fmaf(pz, w1s[128 + k], a0);
            float a1 = b1s[k + 1];
            a1 = fmaf(px, w1s[k + 1], a1);
            a1 = fmaf(py, w1s[64 + k + 1], a1);
            a1 = fmaf(pz, w1s[128 + k + 1], a1);
            float h0 = softplus_fast(a0);
            float h1 = softplus_fast(a1);
            unsigned hi, lo;
            h2split(h0, h1, hi, lo);
            hh_hi[k2 * HPH + pt] = hi;
            hh_lo[k2 * HPH + pt] = lo;
        }
    }
    __syncthreads();

    // ---- layer 2: HMMA m16n8k16, 3-term fp16 split ----
    // 8 warps = 4 q-tiles(16) x 2 pt-halves(64).
    {
        int wid  = tid >> 5;
        int lane = tid & 31;
        int g = lane >> 2;          // group 0..7
        int t = lane & 3;           // thread-in-group
        int mq  = (wid & 3) * 16;   // q-tile base
        int np0 = (wid >> 2) * 64;  // pt-half base

        float c[8][4];
#pragma unroll
        for (int nt = 0; nt < 8; nt++)
#pragma unroll
            for (int i = 0; i < 4; i++) c[nt][i] = 0.0f;

#pragma unroll
        for (int ks = 0; ks < 4; ks++) {       // 4 k-steps of 16
            int kb2 = ks * 8;                  // k2 base (8 pairs = 16 k)
            int a00 = (mq + g) * WPH + kb2 + t;
            int a10 = (mq + g + 8) * WPH + kb2 + t;
            unsigned ahi[4], alo[4];
            ahi[0] = wh_hi[a00];
            ahi[1] = wh_hi[a10];
            ahi[2] = wh_hi[a00 + 4];
            ahi[3] = wh_hi[a10 + 4];
            alo[0] = wh_lo[a00];
            alo[1] = wh_lo[a10];
            alo[2] = wh_lo[a00 + 4];
            alo[3] = wh_lo[a10 + 4];
#pragma unroll
            for (int nt = 0; nt < 8; nt++) {
                int pt0 = np0 + nt * 8;
                int b0i = (kb2 + t) * HPH + pt0 + g;
                int b1i = (kb2 + t + 4) * HPH + pt0 + g;
                unsigned bhi[2], blo[2];
                bhi[0] = hh_hi[b0i];
                bhi[1] = hh_hi[b1i];
                blo[0] = hh_lo[b0i];
                blo[1] = hh_lo[b1i];
                mma_f16(c[nt], ahi, bhi);
                mma_f16(c[nt], ahi, blo);
                mma_f16(c[nt], alo, bhi);
            }
        }

        // epilogue: softplus + layer3, reduce over 8 groups via shfl
        int q_lo = mq + g, q_hi = mq + g + 8;
        float bql = b2s[q_lo], bqh = b2s[q_hi];
        float wql = w3s[q_lo], wqh = w3s[q_hi];
#pragma unroll
        for (int nt = 0; nt < 8; nt++) {
            int pt0 = np0 + nt * 8;
            float s0 = fmaf(softplus_fast(c[nt][0] + bql), wql,
                            softplus_fast(c[nt][2] + bqh) * wqh);
            float s1 = fmaf(softplus_fast(c[nt][1] + bql), wql,
                            softplus_fast(c[nt][3] + bqh) * wqh);
#pragma unroll
            for (int mask = 4; mask <= 16; mask <<= 1) {
                s0 += __shfl_xor_sync(0xffffffffu, s0, mask);
                s1 += __shfl_xor_sync(0xffffffffu, s1, mask);
            }
            if (g == 0) {
                partial[(wid & 3) * 128 + pt0 + 2 * t]     = s0;
                partial[(wid & 3) * 128 + pt0 + 2 * t + 1] = s1;
            }
        }
    }
    __syncthreads();

    // ---- final reduce + write: 128 threads, one per point ----
    if (tid < 128) {
        float s = partial[tid] + partial[128 + tid] +
                  partial[256 + tid] + partial[384 + tid];
        int gp = blockIdx.x * 128 + tid;
        int ray = gp / spr;
        int j   = gp - ray * spr;
        outp[ray * stride + j] = pnorm[tid] - 0.8f + 0.1f * (b3s[0] + s);
    }
}

// ---------------- upsample: one warp per ray --------------------------------
#define UP_PAD 116
__global__ void upsample_kernel(int n, float s_i, int pp) {
    int gwarp = (blockIdx.x * blockDim.x + threadIdx.x) >> 5;
    int lane  = threadIdx.x & 31;
    int wib   = (threadIdx.x >> 5);
    __shared__ float scdf[8 * UP_PAD];
    if (gwarp >= NRAYS) return;

    const float* d  = g_dbuf[pp] + gwarp * MAXS;
    const float* sd = g_sbuf[pp] + gwarp * MAXS;
    int m = n - 1;
    int base = lane * 4;

    float dj[5], sj[5];
#pragma unroll
    for (int i = 0; i < 5; i++) {
        int idx = base + i;
        bool v = idx < n;
        dj[i] = v ? d[idx] : 1.0f;
        sj[i] = v ? sd[idx] : 0.0f;
    }

    float raw[4];
#pragma unroll
    for (int i = 0; i < 4; i++)
        raw[i] = (sj[i + 1] - sj[i]) / (dj[i + 1] - dj[i] + 1e-5f);

    float prevr = __shfl_up_sync(0xffffffffu, raw[3], 1);
    if (lane == 0) prevr = 0.0f;

    float alpha[4];
#pragma unroll
    for (int i = 0; i < 4; i++) {
        float dvv = fminf(prevr, raw[i]);
        prevr = raw[i];
        dvv = fminf(fmaxf(dvv, -10.0f), 0.0f);
        float mid  = 0.5f * (sj[i] + sj[i + 1]);
        float dist = dj[i + 1] - dj[i];
        float pe = mid - dvv * dist * 0.5f;
        float ne = mid + dvv * dist * 0.5f;
        float pc = sigmoid_precise(pe * s_i);
        float nc = sigmoid_precise(ne * s_i);
        alpha[i] = (pc - nc + 1e-5f) / (pc + 1e-5f);
    }

    float Tloc[4], pl = 1.0f;
#pragma unroll
    for (int i = 0; i < 4; i++) {
        Tloc[i] = pl;
        float om = (base + i < m) ? (1.0f - alpha[i] + 1e-10f) : 1.0f;
        pl *= om;
    }
    float v = pl;
#pragma unroll
    for (int off = 1; off < 32; off <<= 1) {
        float t = __shfl_up_sync(0xffffffffu, v, off);
        if (lane >= off) v *= t;
    }
    float exp_ = __shfl_up_sync(0xffffffffu, v, 1);
    if (lane == 0) exp_ = 1.0f;

    float wp[4], sl = 0.0f, sloc[4];
#pragma unroll
    for (int i = 0; i < 4; i++) {
        float T = exp_ * Tloc[i];
        wp[i] = (base + i < m) ? fmaf(alpha[i], T, 1e-5f) : 0.0f;
        sl += wp[i];
        sloc[i] = sl;
    }
    float tot = sl;
#pragma unroll
    for (int off = 16; off > 0; off >>= 1)
        tot += __shfl_xor_sync(0xffffffffu, tot, off);
    float vs = sl;
#pragma unroll
    for (int off = 1; off < 32; off <<= 1) {
        float t = __shfl_up_sync(0xffffffffu, vs, off);
        if (lane >= off) vs += t;
    }
    float exs = __shfl_up_sync(0xffffffffu, vs, 1);
    if (lane == 0) exs = 0.0f;

    float inv = 1.0f / tot;
    float* cdf = scdf + wib * UP_PAD;
    if (lane == 0) cdf[0] = 0.0f;
#pragma unroll
    for (int i = 0; i < 4; i++) {
        int j = base + i;
        if (j < m) cdf[j + 1] = (exs + sloc[i]) * inv;
    }
    __syncwarp();

    if (lane < 16) {
        float u = (float)lane / 15.0f;
        int lo = 0, hi = n;
        while (lo < hi) {
            int mm = (lo + hi) >> 1;
            if (cdf[mm] <= u) lo = mm + 1; else hi = mm;
        }
        int below = lo - 1;
        if (below < 0) below = 0;
        if (below > n - 1) below = n - 1;
        int above = lo;
        if (above > n - 1) above = n - 1;
        float cb = cdf[below], ca = cdf[above];
        float bb = d[below],   ba = d[above];
        float den = ca - cb;
        if (den < 1e-5f) den = 1.0f;
        float t = (u - cb) / den;
        g_dfine[gwarp * 16 + lane] = bb + t * (ba - bb);
    }
}

// ---------------- parallel stable merge (rank & scatter), ping-pong ---------
__global__ void merge_kernel(int n, int pp) {
    int gwarp = (blockIdx.x * blockDim.x + threadIdx.x) >> 5;
    int lane  = threadIdx.x & 31;
    if (gwarp >= NRAYS) return;
    const float* d  = g_dbuf[pp] + gwarp * MAXS;
    const float* sd = g_sbuf[pp] + gwarp * MAXS;
    float* dd = g_dbuf[pp ^ 1] + gwarp * MAXS;
    float* ds = g_sbuf[pp ^ 1] + gwarp * MAXS;
    const float* fd = g_dfine + gwarp * 16;
    const float* fs = g_sdff  + gwarp * 16;

    if (lane < 16) {
        float v = fd[lane];
        int lo = 0, hi = n;                // count old <= v
        while (lo < hi) { int mm = (lo + hi) >> 1; if (d[mm] <= v) lo = mm + 1; else hi = mm; }
        dd[lo + lane] = v;
        ds[lo + lane] = fs[lane];
    }
    for (int a = lane; a < n; a += 32) {
        float v = d[a];
        int lo = 0, hi = 16;               // count new < v
        while (lo < hi) { int mm = (lo + hi) >> 1; if (fd[mm] < v) lo = mm + 1; else hi = mm; }
        dd[a + lo] = v;
        ds[a + lo] = sd[a];
    }
}

// ---------------- final render: compositing + radiance MLP ------------------
__global__ void render_kernel(const float* __restrict__ o,
                              const float* __restrict__ sp,
                              const float* __restrict__ w1, const float* __restrict__ b1,
                              const float* __restrict__ w2, const float* __restrict__ b2,
                              float* __restrict__ out) {
    int r = blockIdx.x;
    int tid = threadIdx.x;
    __shared__ float dsh[128], cdfsh[128], alphash[128], scan[128];
    __shared__ float w1s[384], b1s[64], w2s[192], b2s[3];
    __shared__ float red0[128], red1[128], red2[128];

    for (int i = tid; i < 384; i += 128) w1s[i] = w1[i];
    for (int i = tid; i < 192; i += 128) w2s[i] = w2[i];
    if (tid < 64) b1s[tid] = b1[tid];
    if (tid < 3)  b2s[tid] = b2[tid];

    float s = sp[0];
    float dv = g_dbuf[0][r * MAXS + tid];
    dsh[tid] = dv;
    cdfsh[tid] = sigmoid_precise(g_sbuf[0][r * MAXS + tid] * s);
    __syncthreads();

    float a = 0.0f;
    if (tid < 127)
        a = fmaxf((cdfsh[tid] - cdfsh[tid + 1]) / (cdfsh[tid] + 1e-10f), 0.0f);
    alphash[tid] = a;
    __syncthreads();
    scan[tid] = (tid == 0) ? 1.0f : (1.0f - alphash[tid - 1] + 1e-10f);
    __syncthreads();
#pragma unroll
    for (int off = 1; off < 128; off <<= 1) {
        float t = (tid >= off) ? scan[tid - off] : 1.0f;
        __syncthreads();
        scan[tid] *= t;
        __syncthreads();
    }

    float rr = 0.f, gg = 0.f, bb = 0.f;
    if (tid < 127) {
        float vw = alphash[tid] * scan[tid];
        float dm = 0.5f * (dsh[tid] + dsh[tid + 1]);
        float ox = o[r * 3 + 0], oy = o[r * 3 + 1], oz = o[r * 3 + 2];
        float dx = g_dirs[r * 3 + 0], dy = g_dirs[r * 3 + 1], dz = g_dirs[r * 3 + 2];
        float x0 = fmaf(dm, dx, ox), x1 = fmaf(dm, dy, oy), x2 = fmaf(dm, dz, oz);
        float a0 = b2s[0], a1 = b2s[1], a2 = b2s[2];
#pragma unroll 8
        for (int j = 0; j < 64; j++) {
            float h = b1s[j];
            h = fmaf(x0, w1s[j], h);
            h = fmaf(x1, w1s[64 + j], h);
            h = fmaf(x2, w1s[128 + j], h);
            h = fmaf(dx, w1s[192 + j], h);
            h = fmaf(dy, w1s[256 + j], h);
            h = fmaf(dz, w1s[320 + j], h);
            h = softplus_fast(h);
            a0 = fmaf(h, w2s[j * 3 + 0], a0);
            a1 = fmaf(h, w2s[j * 3 + 1], a1);
            a2 = fmaf(h, w2s[j * 3 + 2], a2);
        }
        rr = sigmoid_fast(a0) * vw;
        gg = sigmoid_fast(a1) * vw;
        bb = sigmoid_fast(a2) * vw;
    }
    red0[tid] = rr; red1[tid] = gg; red2[tid] = bb;
    __syncthreads();
    for (int off = 64; off > 0; off >>= 1) {
        if (tid < off) {
            red0[tid] += red0[tid + off];
            red1[tid] += red1[tid + off];
            red2[tid] += red2[tid + off];
        }
        __syncthreads();
    }
    if (tid < 3) {
        float v = (tid == 0) ? red0[0] : (tid == 1) ? red1[0] : red2[0];
        out[r * 3 + tid] = v;
    }
}

// ---------------- launch ----------------------------------------------------
extern "C" void kernel_launch(void* const* d_in, const int* in_sizes, int n_in,
                              void* d_out, int out_size) {
    const float* rays_o = (const float*)d_in[0];
    const float* rays_d = (const float*)d_in[1];
    const float* nearp  = (const float*)d_in[2];
    const float* farp   = (const float*)d_in[3];
    const float* s_ptr  = (const float*)d_in[4];
    const float* sw1 = (const float*)d_in[5];
    const float* sb1 = (const float*)d_in[6];
    const float* sw2 = (const float*)d_in[7];
    const float* sb2 = (const float*)d_in[8];
    const float* sw3 = (const float*)d_in[9];
    const float* sb3 = (const float*)d_in[10];
    const float* rw1 = (const float*)d_in[11];
    const float* rb1 = (const float*)d_in[12];
    const float* rw2 = (const float*)d_in[13];
    const float* rb2 = (const float*)d_in[14];
    float* out = (float*)d_out;

    const int sdf_smem = SDF_SMEM_WORDS * 4;
    cudaFuncSetAttribute(sdf_kernel,
                         cudaFuncAttributeMaxDynamicSharedMemorySize, sdf_smem);

    init_kernel<<<(NRAYS + 255) / 256, 256>>>(rays_d, nearp, farp);

    int cta_coarse = NRAYS * 64 / 128;   // 128 pts per CTA
    sdf_kernel<<<cta_coarse, 256, sdf_smem>>>(
        rays_o, sw1, sb1, sw2, sb2, sw3, sb3, 0);

    int cta_fine = NRAYS * 16 / 128;
    int warps_grid = (NRAYS * 32 + 255) / 256;   // one warp per ray
    int pp = 0;
    for (int i = 0; i < 4; i++) {
        int n = 64 + 16 * i;
        float si = 64.0f * (float)(1 << i);
        upsample_kernel<<<warps_grid, 256>>>(n, si, pp);
        sdf_kernel<<<cta_fine, 256, sdf_smem>>>(
            rays_o, sw1, sb1, sw2, sb2, sw3, sb3, 1);
        merge_kernel<<<warps_grid, 256>>>(n, pp);
        pp ^= 1;
    }
    // after 4 flips pp == 0: final data in buffer 0
    render_kernel<<<NRAYS, 128>>>(rays_o, s_ptr, rw1, rb1, rw2, rb2, out);
}

// round 15
// speedup vs baseline: 1.2199x; 1.0329x over previous
#include <cuda_runtime.h>
#include <math.h>

#define NRAYS 16384
#define MAXS 128

typedef unsigned long long u64;

// ---------------- scratch (device globals; no allocation allowed) ----------
__device__ float g_dirs[NRAYS * 3];
__device__ float g_dbuf[2][NRAYS * MAXS];
__device__ float g_sbuf[2][NRAYS * MAXS];
__device__ float g_dfine[NRAYS * 16];

// ---------------- math helpers ---------------------------------------------
__device__ __forceinline__ float softplus_fast(float x) {
    float t = __expf(-fabsf(x));
    return fmaxf(x, 0.0f) + __logf(1.0f + t);
}
__device__ __forceinline__ float sigmoid_fast(float x) {
    return __fdividef(1.0f, 1.0f + __expf(-x));
}
__device__ __forceinline__ float sigmoid_precise(float x) {
    return 1.0f / (1.0f + expf(-x));
}

// ---------------- packed f32x2 helpers (Blackwell FFMA2) --------------------
__device__ __forceinline__ u64 pack2(float lo, float hi) {
    u64 r;
    asm("mov.b64 %0, {%1, %2};" : "=l"(r) : "f"(lo), "f"(hi));
    return r;
}
__device__ __forceinline__ void unpack2(u64 v, float& lo, float& hi) {
    asm("mov.b64 {%0, %1}, %2;" : "=f"(lo), "=f"(hi) : "l"(v));
}
__device__ __forceinline__ u64 ffma2(u64 a, u64 b, u64 c) {
    u64 d;
    asm("fma.rn.f32x2 %0, %1, %2, %3;" : "=l"(d) : "l"(a), "l"(b), "l"(c));
    return d;
}

// ---------------- init: normalize dirs, fill coarse d ----------------------
__global__ void init_kernel(const float* __restrict__ rd,
                            const float* __restrict__ nearp,
                            const float* __restrict__ farp) {
    int r = blockIdx.x * blockDim.x + threadIdx.x;
    if (r >= NRAYS) return;
    float dx = rd[r * 3 + 0], dy = rd[r * 3 + 1], dz = rd[r * 3 + 2];
    float nrm = sqrtf(dx * dx + dy * dy + dz * dz);
    dx /= nrm; dy /= nrm; dz /= nrm;
    g_dirs[r * 3 + 0] = dx; g_dirs[r * 3 + 1] = dy; g_dirs[r * 3 + 2] = dz;
    float nr = nearp[r], fr = farp[r];
    for (int j = 0; j < 64; j++) {
        float t = (float)j / 63.0f;
        g_dbuf[0][r * MAXS + j] = nr * (1.0f - t) + fr * t;
    }
}

// ---------------- SDF MLP: block-GEMM, 128 points per CTA, 256 threads ------
// thread tile: 4 pts x 8 q (R11 champion mapping), reg-capped for 4 CTAs/SM.
// mode 1 (fine) fuses the per-ray stable merge (8 rays/CTA, 1 warp/ray).
// smem layout (floats):
//   [0,4096)       w2s  [k][q]
//   [4096,12288)   hsh  [k][pt]  pt=128
//   [12288,13312)  partial [qg=8][pt=128]
//   [13312,13504)  w1s
//   [13504,13568)  b1s
//   [13568,13632)  b2s
//   [13632,13696)  w3s
//   [13696,13824)  pnorm
//   [13824,13952)  dvsh  (fine d values)
//   [13952,14080)  sfsh  (fine sdf values)
//   [14080]        b3s
#define SDF_SMEM_FLOATS 14081
__global__ void __launch_bounds__(256, 4)
sdf_kernel(const float* __restrict__ o,
           const float* __restrict__ w1, const float* __restrict__ b1,
           const float* __restrict__ w2, const float* __restrict__ b2,
           const float* __restrict__ w3, const float* __restrict__ b3,
           int mode, int n, int pp) {
    extern __shared__ __align__(16) float sm[];
    float* w2s    = sm;
    float* hsh    = sm + 4096;
    float* partial= sm + 12288;
    float* w1s    = sm + 13312;
    float* b1s    = sm + 13504;
    float* b2s    = sm + 13568;
    float* w3s    = sm + 13632;
    float* pnorm  = sm + 13696;
    float* dvsh   = sm + 13824;
    float* sfsh   = sm + 13952;
    float* b3s    = sm + 14080;

    int tid = threadIdx.x;
    for (int i = tid; i < 4096; i += 256) w2s[i] = w2[i];
    if (tid < 192) w1s[tid] = w1[tid];
    if (tid < 64) { b1s[tid] = b1[tid]; b2s[tid] = b2[tid]; w3s[tid] = w3[tid]; }
    if (tid == 0) b3s[0] = b3[0];
    __syncthreads();

    const float* dvals = mode ? g_dfine : g_dbuf[0];
    int spr    = mode ? 16 : 64;
    int stride = mode ? 16 : MAXS;

    // ---- layer 1: 256 threads = 128 pts x 2 k-groups of 32 ----
    {
        int pt = tid & 127, kg = tid >> 7;
        int gp = blockIdx.x * 128 + pt;
        int ray = gp / spr;
        int j   = gp - ray * spr;
        float dv = dvals[ray * stride + j];
        float ox = o[ray * 3 + 0], oy = o[ray * 3 + 1], oz = o[ray * 3 + 2];
        float dx = g_dirs[ray * 3 + 0], dy = g_dirs[ray * 3 + 1], dz = g_dirs[ray * 3 + 2];
        float px = fmaf(dv, dx, ox), py = fmaf(dv, dy, oy), pz = fmaf(dv, dz, oz);
        if (kg == 0) {
            pnorm[pt] = sqrtf(fmaf(px, px, fmaf(py, py, pz * pz)));
            dvsh[pt] = dv;
        }
        int k0 = kg * 32;
#pragma unroll
        for (int k = k0; k < k0 + 32; k++) {
            float a = b1s[k];
            a = fmaf(px, w1s[k], a);
            a = fmaf(py, w1s[64 + k], a);
            a = fmaf(pz, w1s[128 + k], a);
            hsh[k * 128 + pt] = softplus_fast(a);
        }
    }
    __syncthreads();

    // ---- layer 2: 256 threads = 32 pt-quads x 8 q-groups of 8 ----
    {
        int pq = tid & 31;          // pts 4pq .. 4pq+3
        int qg = tid >> 5;          // q group (warp-uniform): q0 = qg*8
        int q0 = qg * 8;

        u64 acc[4][4];
#pragma unroll
        for (int i = 0; i < 4; i++)
#pragma unroll
            for (int j = 0; j < 4; j++) acc[i][j] = 0;

#pragma unroll 4
        for (int k = 0; k < 64; k++) {
            float4 h4 = *(const float4*)&hsh[k * 128 + 4 * pq];
            const ulonglong2* wr = (const ulonglong2*)&w2s[k * 64 + q0];
            ulonglong2 wA = wr[0];   // q0..q3 (2 packed pairs)
            ulonglong2 wB = wr[1];   // q4..q7
            u64 h0 = pack2(h4.x, h4.x);
            u64 h1 = pack2(h4.y, h4.y);
            u64 h2 = pack2(h4.z, h4.z);
            u64 h3 = pack2(h4.w, h4.w);
            acc[0][0] = ffma2(h0, wA.x, acc[0][0]);
            acc[0][1] = ffma2(h0, wA.y, acc[0][1]);
            acc[0][2] = ffma2(h0, wB.x, acc[0][2]);
            acc[0][3] = ffma2(h0, wB.y, acc[0][3]);
            acc[1][0] = ffma2(h1, wA.x, acc[1][0]);
            acc[1][1] = ffma2(h1, wA.y, acc[1][1]);
            acc[1][2] = ffma2(h1, wB.x, acc[1][2]);
            acc[1][3] = ffma2(h1, wB.y, acc[1][3]);
            acc[2][0] = ffma2(h2, wA.x, acc[2][0]);
            acc[2][1] = ffma2(h2, wA.y, acc[2][1]);
            acc[2][2] = ffma2(h2, wB.x, acc[2][2]);
            acc[2][3] = ffma2(h2, wB.y, acc[2][3]);
            acc[3][0] = ffma2(h3, wA.x, acc[3][0]);
            acc[3][1] = ffma2(h3, wA.y, acc[3][1]);
            acc[3][2] = ffma2(h3, wB.x, acc[3][2]);
            acc[3][3] = ffma2(h3, wB.y, acc[3][3]);
        }

        // epilogue: softplus + layer3 partials over my 8 q's, 4 pts
        float p0 = 0.f, p1 = 0.f, p2 = 0.f, p3 = 0.f;
#pragma unroll
        for (int j = 0; j < 4; j++) {
            int q = q0 + 2 * j;
            float bql = b2s[q], bqh = b2s[q + 1];
            float wql = w3s[q], wqh = w3s[q + 1];
            float lo, hi;
            unpack2(acc[0][j], lo, hi);
            p0 = fmaf(softplus_fast(lo + bql), wql, p0);
            p0 = fmaf(softplus_fast(hi + bqh), wqh, p0);
            unpack2(acc[1][j], lo, hi);
            p1 = fmaf(softplus_fast(lo + bql), wql, p1);
            p1 = fmaf(softplus_fast(hi + bqh), wqh, p1);
            unpack2(acc[2][j], lo, hi);
            p2 = fmaf(softplus_fast(lo + bql), wql, p2);
            p2 = fmaf(softplus_fast(hi + bqh), wqh, p2);
            unpack2(acc[3][j], lo, hi);
            p3 = fmaf(softplus_fast(lo + bql), wql, p3);
            p3 = fmaf(softplus_fast(hi + bqh), wqh, p3);
        }
        *(float4*)&partial[qg * 128 + 4 * pq] = make_float4(p0, p1, p2, p3);
    }
    __syncthreads();

    // ---- final reduce: 128 threads, one per point ----
    if (tid < 128) {
        float s = 0.0f;
#pragma unroll
        for (int g = 0; g < 8; g++) s += partial[g * 128 + tid];
        float val = pnorm[tid] - 0.8f + 0.1f * (b3s[0] + s);
        if (mode == 0) {
            int gp = blockIdx.x * 128 + tid;
            int ray = gp / spr;
            int j   = gp - ray * spr;
            g_sbuf[0][ray * stride + j] = val;
        } else {
            sfsh[tid] = val;
        }
    }
    if (mode == 0) return;

    // ---- fused stable merge (mode 1): 8 warps = 8 rays, 16 new samples -----
    __syncthreads();
    {
        int w    = tid >> 5;
        int lane = tid & 31;
        int ray  = blockIdx.x * 8 + w;
        const float* d  = g_dbuf[pp] + ray * MAXS;
        const float* sd = g_sbuf[pp] + ray * MAXS;
        float* dd = g_dbuf[pp ^ 1] + ray * MAXS;
        float* ds = g_sbuf[pp ^ 1] + ray * MAXS;
        const float* fd = dvsh + w * 16;
        const float* fs = sfsh + w * 16;

        if (lane < 16) {
            float v = fd[lane];
            int lo = 0, hi = n;                // count old <= v
            while (lo < hi) { int mm = (lo + hi) >> 1; if (d[mm] <= v) lo = mm + 1; else hi = mm; }
            dd[lo + lane] = v;
            ds[lo + lane] = fs[lane];
        }
        for (int a = lane; a < n; a += 32) {
            float v = d[a];
            int lo = 0, hi = 16;               // count new < v
            while (lo < hi) { int mm = (lo + hi) >> 1; if (fd[mm] < v) lo = mm + 1; else hi = mm; }
            dd[a + lo] = v;
            ds[a + lo] = sd[a];
        }
    }
}

// ---------------- upsample: one warp per ray --------------------------------
#define UP_PAD 116
__global__ void upsample_kernel(int n, float s_i, int pp) {
    int gwarp = (blockIdx.x * blockDim.x + threadIdx.x) >> 5;
    int lane  = threadIdx.x & 31;
    int wib   = (threadIdx.x >> 5);
    __shared__ float scdf[8 * UP_PAD];
    if (gwarp >= NRAYS) return;

    const float* d  = g_dbuf[pp] + gwarp * MAXS;
    const float* sd = g_sbuf[pp] + gwarp * MAXS;
    int m = n - 1;
    int base = lane * 4;

    float dj[5], sj[5];
#pragma unroll
    for (int i = 0; i < 5; i++) {
        int idx = base + i;
        bool v = idx < n;
        dj[i] = v ? d[idx] : 1.0f;
        sj[i] = v ? sd[idx] : 0.0f;
    }

    float raw[4];
#pragma unroll
    for (int i = 0; i < 4; i++)
        raw[i] = (sj[i + 1] - sj[i]) / (dj[i + 1] - dj[i] + 1e-5f);

    float prevr = __shfl_up_sync(0xffffffffu, raw[3], 1);
    if (lane == 0) prevr = 0.0f;

    float alpha[4];
#pragma unroll
    for (int i = 0; i < 4; i++) {
        float dvv = fminf(prevr, raw[i]);
        prevr = raw[i];
        dvv = fminf(fmaxf(dvv, -10.0f), 0.0f);
        float mid  = 0.5f * (sj[i] + sj[i + 1]);
        float dist = dj[i + 1] - dj[i];
        float pe = mid - dvv * dist * 0.5f;
        float ne = mid + dvv * dist * 0.5f;
        float pc = sigmoid_precise(pe * s_i);
        float nc = sigmoid_precise(ne * s_i);
        alpha[i] = (pc - nc + 1e-5f) / (pc + 1e-5f);
    }

    float Tloc[4], pl = 1.0f;
#pragma unroll
    for (int i = 0; i < 4; i++) {
        Tloc[i] = pl;
        float om = (base + i < m) ? (1.0f - alpha[i] + 1e-10f) : 1.0f;
        pl *= om;
    }
    float v = pl;
#pragma unroll
    for (int off = 1; off < 32; off <<= 1) {
        float t = __shfl_up_sync(0xffffffffu, v, off);
        if (lane >= off) v *= t;
    }
    float exp_ = __shfl_up_sync(0xffffffffu, v, 1);
    if (lane == 0) exp_ = 1.0f;

    float wp[4], sl = 0.0f, sloc[4];
#pragma unroll
    for (int i = 0; i < 4; i++) {
        float T = exp_ * Tloc[i];
        wp[i] = (base + i < m) ? fmaf(alpha[i], T, 1e-5f) : 0.0f;
        sl += wp[i];
        sloc[i] = sl;
    }
    float tot = sl;
#pragma unroll
    for (int off = 16; off > 0; off >>= 1)
        tot += __shfl_xor_sync(0xffffffffu, tot, off);
    float vs = sl;
#pragma unroll
    for (int off = 1; off < 32; off <<= 1) {
        float t = __shfl_up_sync(0xffffffffu, vs, off);
        if (lane >= off) vs += t;
    }
    float exs = __shfl_up_sync(0xffffffffu, vs, 1);
    if (lane == 0) exs = 0.0f;

    float inv = 1.0f / tot;
    float* cdf = scdf + wib * UP_PAD;
    if (lane == 0) cdf[0] = 0.0f;
#pragma unroll
    for (int i = 0; i < 4; i++) {
        int j = base + i;
        if (j < m) cdf[j + 1] = (exs + sloc[i]) * inv;
    }
    __syncwarp();

    if (lane < 16) {
        float u = (float)lane / 15.0f;
        int lo = 0, hi = n;
        while (lo < hi) {
            int mm = (lo + hi) >> 1;
            if (cdf[mm] <= u) lo = mm + 1; else hi = mm;
        }
        int below = lo - 1;
        if (below < 0) below = 0;
        if (below > n - 1) below = n - 1;
        int above = lo;
        if (above > n - 1) above = n - 1;
        float cb = cdf[below], ca = cdf[above];
        float bb = d[below],   ba = d[above];
        float den = ca - cb;
        if (den < 1e-5f) den = 1.0f;
        float t = (u - cb) / den;
        g_dfine[gwarp * 16 + lane] = bb + t * (ba - bb);
    }
}

// ---------------- final render: compositing + radiance MLP ------------------
__global__ void render_kernel(const float* __restrict__ o,
                              const float* __restrict__ sp,
                              const float* __restrict__ w1, const float* __restrict__ b1,
                              const float* __restrict__ w2, const float* __restrict__ b2,
                              float* __restrict__ out) {
    int r = blockIdx.x;
    int tid = threadIdx.x;
    __shared__ float dsh[128], cdfsh[128], alphash[128], scan[128];
    __shared__ float w1s[384], b1s[64], w2s[192], b2s[3];
    __shared__ float red0[128], red1[128], red2[128];

    for (int i = tid; i < 384; i += 128) w1s[i] = w1[i];
    for (int i = tid; i < 192; i += 128) w2s[i] = w2[i];
    if (tid < 64) b1s[tid] = b1[tid];
    if (tid < 3)  b2s[tid] = b2[tid];

    float s = sp[0];
    float dv = g_dbuf[0][r * MAXS + tid];
    dsh[tid] = dv;
    cdfsh[tid] = sigmoid_precise(g_sbuf[0][r * MAXS + tid] * s);
    __syncthreads();

    float a = 0.0f;
    if (tid < 127)
        a = fmaxf((cdfsh[tid] - cdfsh[tid + 1]) / (cdfsh[tid] + 1e-10f), 0.0f);
    alphash[tid] = a;
    __syncthreads();
    scan[tid] = (tid == 0) ? 1.0f : (1.0f - alphash[tid - 1] + 1e-10f);
    __syncthreads();
#pragma unroll
    for (int off = 1; off < 128; off <<= 1) {
        float t = (tid >= off) ? scan[tid - off] : 1.0f;
        __syncthreads();
        scan[tid] *= t;
        __syncthreads();
    }

    float rr = 0.f, gg = 0.f, bb = 0.f;
    if (tid < 127) {
        float vw = alphash[tid] * scan[tid];
        float dm = 0.5f * (dsh[tid] + dsh[tid + 1]);
        float ox = o[r * 3 + 0], oy = o[r * 3 + 1], oz = o[r * 3 + 2];
        float dx = g_dirs[r * 3 + 0], dy = g_dirs[r * 3 + 1], dz = g_dirs[r * 3 + 2];
        float x0 = fmaf(dm, dx, ox), x1 = fmaf(dm, dy, oy), x2 = fmaf(dm, dz, oz);
        float a0 = b2s[0], a1 = b2s[1], a2 = b2s[2];
#pragma unroll 8
        for (int j = 0; j < 64; j++) {
            float h = b1s[j];
            h = fmaf(x0, w1s[j], h);
            h = fmaf(x1, w1s[64 + j], h);
            h = fmaf(x2, w1s[128 + j], h);
            h = fmaf(dx, w1s[192 + j], h);
            h = fmaf(dy, w1s[256 + j], h);
            h = fmaf(dz, w1s[320 + j], h);
            h = softplus_fast(h);
            a0 = fmaf(h, w2s[j * 3 + 0], a0);
            a1 = fmaf(h, w2s[j * 3 + 1], a1);
            a2 = fmaf(h, w2s[j * 3 + 2], a2);
        }
        rr = sigmoid_fast(a0) * vw;
        gg = sigmoid_fast(a1) * vw;
        bb = sigmoid_fast(a2) * vw;
    }
    red0[tid] = rr; red1[tid] = gg; red2[tid] = bb;
    __syncthreads();
    for (int off = 64; off > 0; off >>= 1) {
        if (tid < off) {
            red0[tid] += red0[tid + off];
            red1[tid] += red1[tid + off];
            red2[tid] += red2[tid + off];
        }
        __syncthreads();
    }
    if (tid < 3) {
        float v = (tid == 0) ? red0[0] : (tid == 1) ? red1[0] : red2[0];
        out[r * 3 + tid] = v;
    }
}

// ---------------- launch ----------------------------------------------------
extern "C" void kernel_launch(void* const* d_in, const int* in_sizes, int n_in,
                              void* d_out, int out_size) {
    const float* rays_o = (const float*)d_in[0];
    const float* rays_d = (const float*)d_in[1];
    const float* nearp  = (const float*)d_in[2];
    const float* farp   = (const float*)d_in[3];
    const float* s_ptr  = (const float*)d_in[4];
    const float* sw1 = (const float*)d_in[5];
    const float* sb1 = (const float*)d_in[6];
    const float* sw2 = (const float*)d_in[7];
    const float* sb2 = (const float*)d_in[8];
    const float* sw3 = (const float*)d_in[9];
    const float* sb3 = (const float*)d_in[10];
    const float* rw1 = (const float*)d_in[11];
    const float* rb1 = (const float*)d_in[12];
    const float* rw2 = (const float*)d_in[13];
    const float* rb2 = (const float*)d_in[14];
    float* out = (float*)d_out;

    const int sdf_smem = SDF_SMEM_FLOATS * 4;
    cudaFuncSetAttribute(sdf_kernel,
                         cudaFuncAttributeMaxDynamicSharedMemorySize, sdf_smem);

    init_kernel<<<(NRAYS + 255) / 256, 256>>>(rays_d, nearp, farp);

    int cta_coarse = NRAYS * 64 / 128;   // 128 pts per CTA
    sdf_kernel<<<cta_coarse, 256, sdf_smem>>>(
        rays_o, sw1, sb1, sw2, sb2, sw3, sb3, 0, 0, 0);

    int cta_fine = NRAYS * 16 / 128;     // 128 pts = 8 rays per CTA
    int warps_grid = (NRAYS * 32 + 255) / 256;   // one warp per ray
    int pp = 0;
    for (int i = 0; i < 4; i++) {
        int n = 64 + 16 * i;
        float si = 64.0f * (float)(1 << i);
        upsample_kernel<<<warps_grid, 256>>>(n, si, pp);
        sdf_kernel<<<cta_fine, 256, sdf_smem>>>(
            rays_o, sw1, sb1, sw2, sb2, sw3, sb3, 1, n, pp);
        pp ^= 1;
    }
    // after 4 flips pp == 0: final data in buffer 0
    render_kernel<<<NRAYS, 128>>>(rays_o, s_ptr, rw1, rb1, rw2, rb2, out);
}

// round 16
// speedup vs baseline: 1.2891x; 1.0567x over previous
#include <cuda_runtime.h>
#include <math.h>

#define NRAYS 16384
#define MAXS 128

typedef unsigned long long u64;

// ---------------- scratch (device globals; no allocation allowed) ----------
__device__ float g_dirs[NRAYS * 3];
__device__ float g_dbuf[2][NRAYS * MAXS];
__device__ float g_sbuf[2][NRAYS * MAXS];
__device__ float g_dfine[NRAYS * 16];
__device__ float g_sdff[NRAYS * 16];

// ---------------- math helpers ---------------------------------------------
__device__ __forceinline__ float softplus_fast(float x) {
    float t = __expf(-fabsf(x));
    return fmaxf(x, 0.0f) + __logf(1.0f + t);
}
__device__ __forceinline__ float sigmoid_fast(float x) {
    return __fdividef(1.0f, 1.0f + __expf(-x));
}
__device__ __forceinline__ float sigmoid_precise(float x) {
    return 1.0f / (1.0f + expf(-x));
}

// ---------------- packed f32x2 helpers (Blackwell FFMA2) --------------------
__device__ __forceinline__ u64 pack2(float lo, float hi) {
    u64 r;
    asm("mov.b64 %0, {%1, %2};" : "=l"(r) : "f"(lo), "f"(hi));
    return r;
}
__device__ __forceinline__ void unpack2(u64 v, float& lo, float& hi) {
    asm("mov.b64 {%0, %1}, %2;" : "=f"(lo), "=f"(hi) : "l"(v));
}
__device__ __forceinline__ u64 ffma2(u64 a, u64 b, u64 c) {
    u64 d;
    asm("fma.rn.f32x2 %0, %1, %2, %3;" : "=l"(d) : "l"(a), "l"(b), "l"(c));
    return d;
}

// ---------------- init: normalize dirs, fill coarse d ----------------------
__global__ void init_kernel(const float* __restrict__ rd,
                            const float* __restrict__ nearp,
                            const float* __restrict__ farp) {
    int r = blockIdx.x * blockDim.x + threadIdx.x;
    if (r >= NRAYS) return;
    float dx = rd[r * 3 + 0], dy = rd[r * 3 + 1], dz = rd[r * 3 + 2];
    float nrm = sqrtf(dx * dx + dy * dy + dz * dz);
    dx /= nrm; dy /= nrm; dz /= nrm;
    g_dirs[r * 3 + 0] = dx; g_dirs[r * 3 + 1] = dy; g_dirs[r * 3 + 2] = dz;
    float nr = nearp[r], fr = farp[r];
    for (int j = 0; j < 64; j++) {
        float t = (float)j / 63.0f;
        g_dbuf[0][r * MAXS + j] = nr * (1.0f - t) + fr * t;
    }
}

// ---------------- SDF MLP: block-GEMM, 128 points per CTA (R11 champion) ----
// smem layout (floats):
//   [0,4096)       w2s  [k][q]
//   [4096,12288)   hsh  [k][pt]  pt=128
//   [12288,13312)  partial [qg=8][pt=128]
//   [13312,13504)  w1s
//   [13504,13568)  b1s
//   [13568,13632)  b2s
//   [13632,13696)  w3s
//   [13696,13824)  pnorm
//   [13824]        b3s
#define SDF_SMEM_FLOATS 13832
__global__ void __launch_bounds__(256, 4)
sdf_kernel(const float* __restrict__ o,
           const float* __restrict__ w1, const float* __restrict__ b1,
           const float* __restrict__ w2, const float* __restrict__ b2,
           const float* __restrict__ w3, const float* __restrict__ b3,
           int mode) {
    extern __shared__ __align__(16) float sm[];
    float* w2s    = sm;
    float* hsh    = sm + 4096;
    float* partial= sm + 12288;
    float* w1s    = sm + 13312;
    float* b1s    = sm + 13504;
    float* b2s    = sm + 13568;
    float* w3s    = sm + 13632;
    float* pnorm  = sm + 13696;
    float* b3s    = sm + 13824;

    int tid = threadIdx.x;
    for (int i = tid; i < 4096; i += 256) w2s[i] = w2[i];
    if (tid < 192) w1s[tid] = w1[tid];
    if (tid < 64) { b1s[tid] = b1[tid]; b2s[tid] = b2[tid]; w3s[tid] = w3[tid]; }
    if (tid == 0) b3s[0] = b3[0];
    __syncthreads();

    const float* dvals = mode ? g_dfine : g_dbuf[0];
    float* outp        = mode ? g_sdff  : g_sbuf[0];
    int spr    = mode ? 16 : 64;
    int stride = mode ? 16 : MAXS;

    // ---- layer 1: 256 threads = 128 pts x 2 k-groups of 32 ----
    {
        int pt = tid & 127, kg = tid >> 7;
        int gp = blockIdx.x * 128 + pt;
        int ray = gp / spr;
        int j   = gp - ray * spr;
        float dv = dvals[ray * stride + j];
        float ox = o[ray * 3 + 0], oy = o[ray * 3 + 1], oz = o[ray * 3 + 2];
        float dx = g_dirs[ray * 3 + 0], dy = g_dirs[ray * 3 + 1], dz = g_dirs[ray * 3 + 2];
        float px = fmaf(dv, dx, ox), py = fmaf(dv, dy, oy), pz = fmaf(dv, dz, oz);
        if (kg == 0)
            pnorm[pt] = sqrtf(fmaf(px, px, fmaf(py, py, pz * pz)));
        int k0 = kg * 32;
#pragma unroll
        for (int k = k0; k < k0 + 32; k++) {
            float a = b1s[k];
            a = fmaf(px, w1s[k], a);
            a = fmaf(py, w1s[64 + k], a);
            a = fmaf(pz, w1s[128 + k], a);
            hsh[k * 128 + pt] = softplus_fast(a);
        }
    }
    __syncthreads();

    // ---- layer 2: 256 threads = 32 pt-quads x 8 q-groups of 8 ----
    {
        int pq = tid & 31;
        int qg = tid >> 5;
        int q0 = qg * 8;

        u64 acc[4][4];
#pragma unroll
        for (int i = 0; i < 4; i++)
#pragma unroll
            for (int j = 0; j < 4; j++) acc[i][j] = 0;

#pragma unroll 4
        for (int k = 0; k < 64; k++) {
            float4 h4 = *(const float4*)&hsh[k * 128 + 4 * pq];
            const ulonglong2* wr = (const ulonglong2*)&w2s[k * 64 + q0];
            ulonglong2 wA = wr[0];
            ulonglong2 wB = wr[1];
            u64 h0 = pack2(h4.x, h4.x);
            u64 h1 = pack2(h4.y, h4.y);
            u64 h2 = pack2(h4.z, h4.z);
            u64 h3 = pack2(h4.w, h4.w);
            acc[0][0] = ffma2(h0, wA.x, acc[0][0]);
            acc[0][1] = ffma2(h0, wA.y, acc[0][1]);
            acc[0][2] = ffma2(h0, wB.x, acc[0][2]);
            acc[0][3] = ffma2(h0, wB.y, acc[0][3]);
            acc[1][0] = ffma2(h1, wA.x, acc[1][0]);
            acc[1][1] = ffma2(h1, wA.y, acc[1][1]);
            acc[1][2] = ffma2(h1, wB.x, acc[1][2]);
            acc[1][3] = ffma2(h1, wB.y, acc[1][3]);
            acc[2][0] = ffma2(h2, wA.x, acc[2][0]);
            acc[2][1] = ffma2(h2, wA.y, acc[2][1]);
            acc[2][2] = ffma2(h2, wB.x, acc[2][2]);
            acc[2][3] = ffma2(h2, wB.y, acc[2][3]);
            acc[3][0] = ffma2(h3, wA.x, acc[3][0]);
            acc[3][1] = ffma2(h3, wA.y, acc[3][1]);
            acc[3][2] = ffma2(h3, wB.x, acc[3][2]);
            acc[3][3] = ffma2(h3, wB.y, acc[3][3]);
        }

        float p0 = 0.f, p1 = 0.f, p2 = 0.f, p3 = 0.f;
#pragma unroll
        for (int j = 0; j < 4; j++) {
            int q = q0 + 2 * j;
            float bql = b2s[q], bqh = b2s[q + 1];
            float wql = w3s[q], wqh = w3s[q + 1];
            float lo, hi;
            unpack2(acc[0][j], lo, hi);
            p0 = fmaf(softplus_fast(lo + bql), wql, p0);
            p0 = fmaf(softplus_fast(hi + bqh), wqh, p0);
            unpack2(acc[1][j], lo, hi);
            p1 = fmaf(softplus_fast(lo + bql), wql, p1);
            p1 = fmaf(softplus_fast(hi + bqh), wqh, p1);
            unpack2(acc[2][j], lo, hi);
            p2 = fmaf(softplus_fast(lo + bql), wql, p2);
            p2 = fmaf(softplus_fast(hi + bqh), wqh, p2);
            unpack2(acc[3][j], lo, hi);
            p3 = fmaf(softplus_fast(lo + bql), wql, p3);
            p3 = fmaf(softplus_fast(hi + bqh), wqh, p3);
        }
        *(float4*)&partial[qg * 128 + 4 * pq] = make_float4(p0, p1, p2, p3);
    }
    __syncthreads();

    if (tid < 128) {
        float s = 0.0f;
#pragma unroll
        for (int g = 0; g < 8; g++) s += partial[g * 128 + tid];
        int gp = blockIdx.x * 128 + tid;
        int ray = gp / spr;
        int j   = gp - ray * spr;
        outp[ray * stride + j] = pnorm[tid] - 0.8f + 0.1f * (b3s[0] + s);
    }
}

// ---------------- upsample body (shared by standalone & fused) --------------
// d/sd: per-ray arrays (global or smem); cdf: per-warp smem scratch
__device__ __forceinline__ void upsample_body(
    const float* d, const float* sd, float* cdf,
    int n, float s_i, int lane, float* dfine_out) {
    int m = n - 1;
    int base = lane * 4;

    float dj[5], sj[5];
#pragma unroll
    for (int i = 0; i < 5; i++) {
        int idx = base + i;
        bool v = idx < n;
        dj[i] = v ? d[idx] : 1.0f;
        sj[i] = v ? sd[idx] : 0.0f;
    }

    float raw[4];
#pragma unroll
    for (int i = 0; i < 4; i++)
        raw[i] = (sj[i + 1] - sj[i]) / (dj[i + 1] - dj[i] + 1e-5f);

    float prevr = __shfl_up_sync(0xffffffffu, raw[3], 1);
    if (lane == 0) prevr = 0.0f;

    float alpha[4];
#pragma unroll
    for (int i = 0; i < 4; i++) {
        float dvv = fminf(prevr, raw[i]);
        prevr = raw[i];
        dvv = fminf(fmaxf(dvv, -10.0f), 0.0f);
        float mid  = 0.5f * (sj[i] + sj[i + 1]);
        float dist = dj[i + 1] - dj[i];
        float pe = mid - dvv * dist * 0.5f;
        float ne = mid + dvv * dist * 0.5f;
        float pc = sigmoid_precise(pe * s_i);
        float nc = sigmoid_precise(ne * s_i);
        alpha[i] = (pc - nc + 1e-5f) / (pc + 1e-5f);
    }

    float Tloc[4], pl = 1.0f;
#pragma unroll
    for (int i = 0; i < 4; i++) {
        Tloc[i] = pl;
        float om = (base + i < m) ? (1.0f - alpha[i] + 1e-10f) : 1.0f;
        pl *= om;
    }
    float v = pl;
#pragma unroll
    for (int off = 1; off < 32; off <<= 1) {
        float t = __shfl_up_sync(0xffffffffu, v, off);
        if (lane >= off) v *= t;
    }
    float exp_ = __shfl_up_sync(0xffffffffu, v, 1);
    if (lane == 0) exp_ = 1.0f;

    float wp[4], sl = 0.0f, sloc[4];
#pragma unroll
    for (int i = 0; i < 4; i++) {
        float T = exp_ * Tloc[i];
        wp[i] = (base + i < m) ? fmaf(alpha[i], T, 1e-5f) : 0.0f;
        sl += wp[i];
        sloc[i] = sl;
    }
    float tot = sl;
#pragma unroll
    for (int off = 16; off > 0; off >>= 1)
        tot += __shfl_xor_sync(0xffffffffu, tot, off);
    float vs = sl;
#pragma unroll
    for (int off = 1; off < 32; off <<= 1) {
        float t = __shfl_up_sync(0xffffffffu, vs, off);
        if (lane >= off) vs += t;
    }
    float exs = __shfl_up_sync(0xffffffffu, vs, 1);
    if (lane == 0) exs = 0.0f;

    float inv = 1.0f / tot;
    if (lane == 0) cdf[0] = 0.0f;
#pragma unroll
    for (int i = 0; i < 4; i++) {
        int j = base + i;
        if (j < m) cdf[j + 1] = (exs + sloc[i]) * inv;
    }
    __syncwarp();

    if (lane < 16) {
        float u = (float)lane / 15.0f;
        int lo = 0, hi = n;
        while (lo < hi) {
            int mm = (lo + hi) >> 1;
            if (cdf[mm] <= u) lo = mm + 1; else hi = mm;
        }
        int below = lo - 1;
        if (below < 0) below = 0;
        if (below > n - 1) below = n - 1;
        int above = lo;
        if (above > n - 1) above = n - 1;
        float cb = cdf[below], ca = cdf[above];
        float bb = d[below],   ba = d[above];
        float den = ca - cb;
        if (den < 1e-5f) den = 1.0f;
        float t = (u - cb) / den;
        dfine_out[lane] = bb + t * (ba - bb);
    }
}

// ---------------- standalone upsample (iter 0) ------------------------------
#define UP_PAD 116
__global__ void upsample_kernel(int n, float s_i, int pp) {
    int gwarp = (blockIdx.x * blockDim.x + threadIdx.x) >> 5;
    int lane  = threadIdx.x & 31;
    int wib   = (threadIdx.x >> 5);
    __shared__ float scdf[8 * UP_PAD];
    if (gwarp >= NRAYS) return;
    upsample_body(g_dbuf[pp] + gwarp * MAXS, g_sbuf[pp] + gwarp * MAXS,
                  scdf + wib * UP_PAD, n, s_i, lane, g_dfine + gwarp * 16);
}

// ---------------- fused: merge(n_old) then upsample(n_old+16) ---------------
__global__ void fused_merge_upsample(int n_old, float s_i, int pp) {
    int gwarp = (blockIdx.x * blockDim.x + threadIdx.x) >> 5;
    int lane  = threadIdx.x & 31;
    int wib   = (threadIdx.x >> 5);
    __shared__ float dm[8][128], smm[8][128], scdf[8 * UP_PAD];
    if (gwarp >= NRAYS) return;

    const float* d  = g_dbuf[pp] + gwarp * MAXS;
    const float* sd = g_sbuf[pp] + gwarp * MAXS;
    float* dd = g_dbuf[pp ^ 1] + gwarp * MAXS;
    float* ds = g_sbuf[pp ^ 1] + gwarp * MAXS;
    const float* fd = g_dfine + gwarp * 16;
    const float* fs = g_sdff  + gwarp * 16;
    float* dmw = dm[wib];
    float* smw = smm[wib];

    // stable merge (same semantics as before): new after equal old
    if (lane < 16) {
        float v = fd[lane];
        int lo = 0, hi = n_old;            // count old <= v
        while (lo < hi) { int mm = (lo + hi) >> 1; if (d[mm] <= v) lo = mm + 1; else hi = mm; }
        int pos = lo + lane;
        float sv = fs[lane];
        dd[pos] = v;  ds[pos] = sv;
        dmw[pos] = v; smw[pos] = sv;
    }
    for (int a = lane; a < n_old; a += 32) {
        float v = d[a];
        int lo = 0, hi = 16;               // count new < v
        while (lo < hi) { int mm = (lo + hi) >> 1; if (fd[mm] < v) lo = mm + 1; else hi = mm; }
        int pos = a + lo;
        float sv = sd[a];
        dd[pos] = v;  ds[pos] = sv;
        dmw[pos] = v; smw[pos] = sv;
    }
    __syncwarp();

    // upsample from the freshly merged smem arrays
    upsample_body(dmw, smw, scdf + wib * UP_PAD,
                  n_old + 16, s_i, lane, g_dfine + gwarp * 16);
}

// ---------------- final merge (after last fine sdf) --------------------------
__global__ void merge_kernel(int n, int pp) {
    int gwarp = (blockIdx.x * blockDim.x + threadIdx.x) >> 5;
    int lane  = threadIdx.x & 31;
    if (gwarp >= NRAYS) return;
    const float* d  = g_dbuf[pp] + gwarp * MAXS;
    const float* sd = g_sbuf[pp] + gwarp * MAXS;
    float* dd = g_dbuf[pp ^ 1] + gwarp * MAXS;
    float* ds = g_sbuf[pp ^ 1] + gwarp * MAXS;
    const float* fd = g_dfine + gwarp * 16;
    const float* fs = g_sdff  + gwarp * 16;

    if (lane < 16) {
        float v = fd[lane];
        int lo = 0, hi = n;
        while (lo < hi) { int mm = (lo + hi) >> 1; if (d[mm] <= v) lo = mm + 1; else hi = mm; }
        dd[lo + lane] = v;
        ds[lo + lane] = fs[lane];
    }
    for (int a = lane; a < n; a += 32) {
        float v = d[a];
        int lo = 0, hi = 16;
        while (lo < hi) { int mm = (lo + hi) >> 1; if (fd[mm] < v) lo = mm + 1; else hi = mm; }
        dd[a + lo] = v;
        ds[a + lo] = sd[a];
    }
}

// ---------------- final render: compositing + radiance MLP ------------------
__global__ void render_kernel(const float* __restrict__ o,
                              const float* __restrict__ sp,
                              const float* __restrict__ w1, const float* __restrict__ b1,
                              const float* __restrict__ w2, const float* __restrict__ b2,
                              float* __restrict__ out) {
    int r = blockIdx.x;
    int tid = threadIdx.x;
    __shared__ float dsh[128], cdfsh[128], alphash[128], scan[128];
    __shared__ float w1s[384], b1s[64], w2s[192], b2s[3];
    __shared__ float red0[128], red1[128], red2[128];

    for (int i = tid; i < 384; i += 128) w1s[i] = w1[i];
    for (int i = tid; i < 192; i += 128) w2s[i] = w2[i];
    if (tid < 64) b1s[tid] = b1[tid];
    if (tid < 3)  b2s[tid] = b2[tid];

    float s = sp[0];
    float dv = g_dbuf[0][r * MAXS + tid];
    dsh[tid] = dv;
    cdfsh[tid] = sigmoid_precise(g_sbuf[0][r * MAXS + tid] * s);
    __syncthreads();

    float a = 0.0f;
    if (tid < 127)
        a = fmaxf((cdfsh[tid] - cdfsh[tid + 1]) / (cdfsh[tid] + 1e-10f), 0.0f);
    alphash[tid] = a;
    __syncthreads();
    scan[tid] = (tid == 0) ? 1.0f : (1.0f - alphash[tid - 1] + 1e-10f);
    __syncthreads();
#pragma unroll
    for (int off = 1; off < 128; off <<= 1) {
        float t = (tid >= off) ? scan[tid - off] : 1.0f;
        __syncthreads();
        scan[tid] *= t;
        __syncthreads();
    }

    float rr = 0.f, gg = 0.f, bb = 0.f;
    if (tid < 127) {
        float vw = alphash[tid] * scan[tid];
        float dm = 0.5f * (dsh[tid] + dsh[tid + 1]);
        float ox = o[r * 3 + 0], oy = o[r * 3 + 1], oz = o[r * 3 + 2];
        float dx = g_dirs[r * 3 + 0], dy = g_dirs[r * 3 + 1], dz = g_dirs[r * 3 + 2];
        float x0 = fmaf(dm, dx, ox), x1 = fmaf(dm, dy, oy), x2 = fmaf(dm, dz, oz);
        float a0 = b2s[0], a1 = b2s[1], a2 = b2s[2];
#pragma unroll 8
        for (int j = 0; j < 64; j++) {
            float h = b1s[j];
            h = fmaf(x0, w1s[j], h);
            h = fmaf(x1, w1s[64 + j], h);
            h = fmaf(x2, w1s[128 + j], h);
            h = fmaf(dx, w1s[192 + j], h);
            h = fmaf(dy, w1s[256 + j], h);
            h = fmaf(dz, w1s[320 + j], h);
            h = softplus_fast(h);
            a0 = fmaf(h, w2s[j * 3 + 0], a0);
            a1 = fmaf(h, w2s[j * 3 + 1], a1);
            a2 = fmaf(h, w2s[j * 3 + 2], a2);
        }
        rr = sigmoid_fast(a0) * vw;
        gg = sigmoid_fast(a1) * vw;
        bb = sigmoid_fast(a2) * vw;
    }
    red0[tid] = rr; red1[tid] = gg; red2[tid] = bb;
    __syncthreads();
    for (int off = 64; off > 0; off >>= 1) {
        if (tid < off) {
            red0[tid] += red0[tid + off];
            red1[tid] += red1[tid + off];
            red2[tid] += red2[tid + off];
        }
        __syncthreads();
    }
    if (tid < 3) {
        float v = (tid == 0) ? red0[0] : (tid == 1) ? red1[0] : red2[0];
        out[r * 3 + tid] = v;
    }
}

// ---------------- launch ----------------------------------------------------
extern "C" void kernel_launch(void* const* d_in, const int* in_sizes, int n_in,
                              void* d_out, int out_size) {
    const float* rays_o = (const float*)d_in[0];
    const float* rays_d = (const float*)d_in[1];
    const float* nearp  = (const float*)d_in[2];
    const float* farp   = (const float*)d_in[3];
    const float* s_ptr  = (const float*)d_in[4];
    const float* sw1 = (const float*)d_in[5];
    const float* sb1 = (const float*)d_in[6];
    const float* sw2 = (const float*)d_in[7];
    const float* sb2 = (const float*)d_in[8];
    const float* sw3 = (const float*)d_in[9];
    const float* sb3 = (const float*)d_in[10];
    const float* rw1 = (const float*)d_in[11];
    const float* rb1 = (const float*)d_in[12];
    const float* rw2 = (const float*)d_in[13];
    const float* rb2 = (const float*)d_in[14];
    float* out = (float*)d_out;

    const int sdf_smem = SDF_SMEM_FLOATS * 4;
    cudaFuncSetAttribute(sdf_kernel,
                         cudaFuncAttributeMaxDynamicSharedMemorySize, sdf_smem);

    init_kernel<<<(NRAYS + 255) / 256, 256>>>(rays_d, nearp, farp);

    int cta_coarse = NRAYS * 64 / 128;   // 128 pts per CTA
    sdf_kernel<<<cta_coarse, 256, sdf_smem>>>(
        rays_o, sw1, sb1, sw2, sb2, sw3, sb3, 0);

    int cta_fine = NRAYS * 16 / 128;
    int warps_grid = (NRAYS * 32 + 255) / 256;   // one warp per ray

    // iter 0: upsample from coarse (buffer 0)
    upsample_kernel<<<warps_grid, 256>>>(64, 64.0f, 0);
    sdf_kernel<<<cta_fine, 256, sdf_smem>>>(
        rays_o, sw1, sb1, sw2, sb2, sw3, sb3, 1);

    // iters 1..3: fused merge(prev) + upsample(next)
    int pp = 0;
    for (int i = 1; i < 4; i++) {
        int n_old = 64 + 16 * (i - 1);
        float si = 64.0f * (float)(1 << i);
        fused_merge_upsample<<<warps_grid, 256>>>(n_old, si, pp);
        pp ^= 1;
        sdf_kernel<<<cta_fine, 256, sdf_smem>>>(
            rays_o, sw1, sb1, sw2, sb2, sw3, sb3, 1);
    }

    // final merge: n_old = 112, pp=1 -> buffer 0
    merge_kernel<<<warps_grid, 256>>>(112, pp);

    render_kernel<<<NRAYS, 128>>>(rays_o, s_ptr, rw1, rb1, rw2, rb2, out);
}

// round 17
// speedup vs baseline: 1.2929x; 1.0030x over previous
#include <cuda_runtime.h>
#include <math.h>

#define NRAYS 16384
#define MAXS 128

typedef unsigned long long u64;

// ---------------- scratch (device globals; no allocation allowed) ----------
__device__ float g_dirs[NRAYS * 3];
__device__ float g_dbuf[2][NRAYS * MAXS];
__device__ float g_sbuf[2][NRAYS * MAXS];
__device__ float g_dfine[NRAYS * 16];
__device__ float g_sdff[NRAYS * 16];

// ---------------- math helpers ---------------------------------------------
__device__ __forceinline__ float softplus_fast(float x) {
    float t = __expf(-fabsf(x));
    return fmaxf(x, 0.0f) + __logf(1.0f + t);
}
__device__ __forceinline__ float sigmoid_fast(float x) {
    return __fdividef(1.0f, 1.0f + __expf(-x));
}
__device__ __forceinline__ float sigmoid_precise(float x) {
    return 1.0f / (1.0f + expf(-x));
}

// ---------------- packed f32x2 helpers (Blackwell FFMA2) --------------------
__device__ __forceinline__ u64 pack2(float lo, float hi) {
    u64 r;
    asm("mov.b64 %0, {%1, %2};" : "=l"(r) : "f"(lo), "f"(hi));
    return r;
}
__device__ __forceinline__ void unpack2(u64 v, float& lo, float& hi) {
    asm("mov.b64 {%0, %1}, %2;" : "=f"(lo), "=f"(hi) : "l"(v));
}
__device__ __forceinline__ u64 ffma2(u64 a, u64 b, u64 c) {
    u64 d;
    asm("fma.rn.f32x2 %0, %1, %2, %3;" : "=l"(d) : "l"(a), "l"(b), "l"(c));
    return d;
}

// ---------------- init: normalize dirs, fill coarse d ----------------------
__global__ void init_kernel(const float* __restrict__ rd,
                            const float* __restrict__ nearp,
                            const float* __restrict__ farp) {
    int r = blockIdx.x * blockDim.x + threadIdx.x;
    if (r >= NRAYS) return;
    float dx = rd[r * 3 + 0], dy = rd[r * 3 + 1], dz = rd[r * 3 + 2];
    float nrm = sqrtf(dx * dx + dy * dy + dz * dz);
    dx /= nrm; dy /= nrm; dz /= nrm;
    g_dirs[r * 3 + 0] = dx; g_dirs[r * 3 + 1] = dy; g_dirs[r * 3 + 2] = dz;
    float nr = nearp[r], fr = farp[r];
    for (int j = 0; j < 64; j++) {
        float t = (float)j / 63.0f;
        g_dbuf[0][r * MAXS + j] = nr * (1.0f - t) + fr * t;
    }
}

// ---------------- SDF MLP: block-GEMM, 128 points per CTA (R11 champion) ----
#define SDF_SMEM_FLOATS 13832
__global__ void __launch_bounds__(256, 4)
sdf_kernel(const float* __restrict__ o,
           const float* __restrict__ w1, const float* __restrict__ b1,
           const float* __restrict__ w2, const float* __restrict__ b2,
           const float* __restrict__ w3, const float* __restrict__ b3,
           int mode) {
    extern __shared__ __align__(16) float sm[];
    float* w2s    = sm;
    float* hsh    = sm + 4096;
    float* partial= sm + 12288;
    float* w1s    = sm + 13312;
    float* b1s    = sm + 13504;
    float* b2s    = sm + 13568;
    float* w3s    = sm + 13632;
    float* pnorm  = sm + 13696;
    float* b3s    = sm + 13824;

    int tid = threadIdx.x;
    for (int i = tid; i < 4096; i += 256) w2s[i] = w2[i];
    if (tid < 192) w1s[tid] = w1[tid];
    if (tid < 64) { b1s[tid] = b1[tid]; b2s[tid] = b2[tid]; w3s[tid] = w3[tid]; }
    if (tid == 0) b3s[0] = b3[0];
    __syncthreads();

    const float* dvals = mode ? g_dfine : g_dbuf[0];
    float* outp        = mode ? g_sdff  : g_sbuf[0];
    int spr    = mode ? 16 : 64;
    int stride = mode ? 16 : MAXS;

    {
        int pt = tid & 127, kg = tid >> 7;
        int gp = blockIdx.x * 128 + pt;
        int ray = gp / spr;
        int j   = gp - ray * spr;
        float dv = dvals[ray * stride + j];
        float ox = o[ray * 3 + 0], oy = o[ray * 3 + 1], oz = o[ray * 3 + 2];
        float dx = g_dirs[ray * 3 + 0], dy = g_dirs[ray * 3 + 1], dz = g_dirs[ray * 3 + 2];
        float px = fmaf(dv, dx, ox), py = fmaf(dv, dy, oy), pz = fmaf(dv, dz, oz);
        if (kg == 0)
            pnorm[pt] = sqrtf(fmaf(px, px, fmaf(py, py, pz * pz)));
        int k0 = kg * 32;
#pragma unroll
        for (int k = k0; k < k0 + 32; k++) {
            float a = b1s[k];
            a = fmaf(px, w1s[k], a);
            a = fmaf(py, w1s[64 + k], a);
            a = fmaf(pz, w1s[128 + k], a);
            hsh[k * 128 + pt] = softplus_fast(a);
        }
    }
    __syncthreads();

    {
        int pq = tid & 31;
        int qg = tid >> 5;
        int q0 = qg * 8;

        u64 acc[4][4];
#pragma unroll
        for (int i = 0; i < 4; i++)
#pragma unroll
            for (int j = 0; j < 4; j++) acc[i][j] = 0;

#pragma unroll 4
        for (int k = 0; k < 64; k++) {
            float4 h4 = *(const float4*)&hsh[k * 128 + 4 * pq];
            const ulonglong2* wr = (const ulonglong2*)&w2s[k * 64 + q0];
            ulonglong2 wA = wr[0];
            ulonglong2 wB = wr[1];
            u64 h0 = pack2(h4.x, h4.x);
            u64 h1 = pack2(h4.y, h4.y);
            u64 h2 = pack2(h4.z, h4.z);
            u64 h3 = pack2(h4.w, h4.w);
            acc[0][0] = ffma2(h0, wA.x, acc[0][0]);
            acc[0][1] = ffma2(h0, wA.y, acc[0][1]);
            acc[0][2] = ffma2(h0, wB.x, acc[0][2]);
            acc[0][3] = ffma2(h0, wB.y, acc[0][3]);
            acc[1][0] = ffma2(h1, wA.x, acc[1][0]);
            acc[1][1] = ffma2(h1, wA.y, acc[1][1]);
            acc[1][2] = ffma2(h1, wB.x, acc[1][2]);
            acc[1][3] = ffma2(h1, wB.y, acc[1][3]);
            acc[2][0] = ffma2(h2, wA.x, acc[2][0]);
            acc[2][1] = ffma2(h2, wA.y, acc[2][1]);
            acc[2][2] = ffma2(h2, wB.x, acc[2][2]);
            acc[2][3] = ffma2(h2, wB.y, acc[2][3]);
            acc[3][0] = ffma2(h3, wA.x, acc[3][0]);
            acc[3][1] = ffma2(h3, wA.y, acc[3][1]);
            acc[3][2] = ffma2(h3, wB.x, acc[3][2]);
            acc[3][3] = ffma2(h3, wB.y, acc[3][3]);
        }

        float p0 = 0.f, p1 = 0.f, p2 = 0.f, p3 = 0.f;
#pragma unroll
        for (int j = 0; j < 4; j++) {
            int q = q0 + 2 * j;
            float bql = b2s[q], bqh = b2s[q + 1];
            float wql = w3s[q], wqh = w3s[q + 1];
            float lo, hi;
            unpack2(acc[0][j], lo, hi);
            p0 = fmaf(softplus_fast(lo + bql), wql, p0);
            p0 = fmaf(softplus_fast(hi + bqh), wqh, p0);
            unpack2(acc[1][j], lo, hi);
            p1 = fmaf(softplus_fast(lo + bql), wql, p1);
            p1 = fmaf(softplus_fast(hi + bqh), wqh, p1);
            unpack2(acc[2][j], lo, hi);
            p2 = fmaf(softplus_fast(lo + bql), wql, p2);
            p2 = fmaf(softplus_fast(hi + bqh), wqh, p2);
            unpack2(acc[3][j], lo, hi);
            p3 = fmaf(softplus_fast(lo + bql), wql, p3);
            p3 = fmaf(softplus_fast(hi + bqh), wqh, p3);
        }
        *(float4*)&partial[qg * 128 + 4 * pq] = make_float4(p0, p1, p2, p3);
    }
    __syncthreads();

    if (tid < 128) {
        float s = 0.0f;
#pragma unroll
        for (int g = 0; g < 8; g++) s += partial[g * 128 + tid];
        int gp = blockIdx.x * 128 + tid;
        int ray = gp / spr;
        int j   = gp - ray * spr;
        outp[ray * stride + j] = pnorm[tid] - 0.8f + 0.1f * (b3s[0] + s);
    }
}

// ---------------- upsample body (shared) -------------------------------------
__device__ __forceinline__ void upsample_body(
    const float* d, const float* sd, float* cdf,
    int n, float s_i, int lane, float* dfine_out) {
    int m = n - 1;
    int base = lane * 4;

    float dj[5], sj[5];
#pragma unroll
    for (int i = 0; i < 5; i++) {
        int idx = base + i;
        bool v = idx < n;
        dj[i] = v ? d[idx] : 1.0f;
        sj[i] = v ? sd[idx] : 0.0f;
    }

    float raw[4];
#pragma unroll
    for (int i = 0; i < 4; i++)
        raw[i] = (sj[i + 1] - sj[i]) / (dj[i + 1] - dj[i] + 1e-5f);

    float prevr = __shfl_up_sync(0xffffffffu, raw[3], 1);
    if (lane == 0) prevr = 0.0f;

    float alpha[4];
#pragma unroll
    for (int i = 0; i < 4; i++) {
        float dvv = fminf(prevr, raw[i]);
        prevr = raw[i];
        dvv = fminf(fmaxf(dvv, -10.0f), 0.0f);
        float mid  = 0.5f * (sj[i] + sj[i + 1]);
        float dist = dj[i + 1] - dj[i];
        float pe = mid - dvv * dist * 0.5f;
        float ne = mid + dvv * dist * 0.5f;
        float pc = sigmoid_precise(pe * s_i);
        float nc = sigmoid_precise(ne * s_i);
        alpha[i] = (pc - nc + 1e-5f) / (pc + 1e-5f);
    }

    float Tloc[4], pl = 1.0f;
#pragma unroll
    for (int i = 0; i < 4; i++) {
        Tloc[i] = pl;
        float om = (base + i < m) ? (1.0f - alpha[i] + 1e-10f) : 1.0f;
        pl *= om;
    }
    float v = pl;
#pragma unroll
    for (int off = 1; off < 32; off <<= 1) {
        float t = __shfl_up_sync(0xffffffffu, v, off);
        if (lane >= off) v *= t;
    }
    float exp_ = __shfl_up_sync(0xffffffffu, v, 1);
    if (lane == 0) exp_ = 1.0f;

    float wp[4], sl = 0.0f, sloc[4];
#pragma unroll
    for (int i = 0; i < 4; i++) {
        float T = exp_ * Tloc[i];
        wp[i] = (base + i < m) ? fmaf(alpha[i], T, 1e-5f) : 0.0f;
        sl += wp[i];
        sloc[i] = sl;
    }
    float tot = sl;
#pragma unroll
    for (int off = 16; off > 0; off >>= 1)
        tot += __shfl_xor_sync(0xffffffffu, tot, off);
    float vs = sl;
#pragma unroll
    for (int off = 1; off < 32; off <<= 1) {
        float t = __shfl_up_sync(0xffffffffu, vs, off);
        if (lane >= off) vs += t;
    }
    float exs = __shfl_up_sync(0xffffffffu, vs, 1);
    if (lane == 0) exs = 0.0f;

    float inv = 1.0f / tot;
    if (lane == 0) cdf[0] = 0.0f;
#pragma unroll
    for (int i = 0; i < 4; i++) {
        int j = base + i;
        if (j < m) cdf[j + 1] = (exs + sloc[i]) * inv;
    }
    __syncwarp();

    if (lane < 16) {
        float u = (float)lane / 15.0f;
        int lo = 0, hi = n;
        while (lo < hi) {
            int mm = (lo + hi) >> 1;
            if (cdf[mm] <= u) lo = mm + 1; else hi = mm;
        }
        int below = lo - 1;
        if (below < 0) below = 0;
        if (below > n - 1) below = n - 1;
        int above = lo;
        if (above > n - 1) above = n - 1;
        float cb = cdf[below], ca = cdf[above];
        float bb = d[below],   ba = d[above];
        float den = ca - cb;
        if (den < 1e-5f) den = 1.0f;
        float t = (u - cb) / den;
        dfine_out[lane] = bb + t * (ba - bb);
    }
}

// ---------------- standalone upsample (iter 0) ------------------------------
#define UP_PAD 116
__global__ void upsample_kernel(int n, float s_i, int pp) {
    int gwarp = (blockIdx.x * blockDim.x + threadIdx.x) >> 5;
    int lane  = threadIdx.x & 31;
    int wib   = (threadIdx.x >> 5);
    __shared__ float scdf[8 * UP_PAD];
    if (gwarp >= NRAYS) return;
    upsample_body(g_dbuf[pp] + gwarp * MAXS, g_sbuf[pp] + gwarp * MAXS,
                  scdf + wib * UP_PAD, n, s_i, lane, g_dfine + gwarp * 16);
}

// ---------------- fused: merge(n_old) then upsample(n_old+16) ---------------
__global__ void fused_merge_upsample(int n_old, float s_i, int pp) {
    int gwarp = (blockIdx.x * blockDim.x + threadIdx.x) >> 5;
    int lane  = threadIdx.x & 31;
    int wib   = (threadIdx.x >> 5);
    __shared__ float dm[8][128], smm[8][128], scdf[8 * UP_PAD];
    if (gwarp >= NRAYS) return;

    const float* d  = g_dbuf[pp] + gwarp * MAXS;
    const float* sd = g_sbuf[pp] + gwarp * MAXS;
    float* dd = g_dbuf[pp ^ 1] + gwarp * MAXS;
    float* ds = g_sbuf[pp ^ 1] + gwarp * MAXS;
    const float* fd = g_dfine + gwarp * 16;
    const float* fs = g_sdff  + gwarp * 16;
    float* dmw = dm[wib];
    float* smw = smm[wib];

    if (lane < 16) {
        float v = fd[lane];
        int lo = 0, hi = n_old;
        while (lo < hi) { int mm = (lo + hi) >> 1; if (d[mm] <= v) lo = mm + 1; else hi = mm; }
        int pos = lo + lane;
        float sv = fs[lane];
        dd[pos] = v;  ds[pos] = sv;
        dmw[pos] = v; smw[pos] = sv;
    }
    for (int a = lane; a < n_old; a += 32) {
        float v = d[a];
        int lo = 0, hi = 16;
        while (lo < hi) { int mm = (lo + hi) >> 1; if (fd[mm] < v) lo = mm + 1; else hi = mm; }
        int pos = a + lo;
        float sv = sd[a];
        dd[pos] = v;  ds[pos] = sv;
        dmw[pos] = v; smw[pos] = sv;
    }
    __syncwarp();

    upsample_body(dmw, smw, scdf + wib * UP_PAD,
                  n_old + 16, s_i, lane, g_dfine + gwarp * 16);
}

// ---------------- final merge (after last fine sdf) --------------------------
__global__ void merge_kernel(int n, int pp) {
    int gwarp = (blockIdx.x * blockDim.x + threadIdx.x) >> 5;
    int lane  = threadIdx.x & 31;
    if (gwarp >= NRAYS) return;
    const float* d  = g_dbuf[pp] + gwarp * MAXS;
    const float* sd = g_sbuf[pp] + gwarp * MAXS;
    float* dd = g_dbuf[pp ^ 1] + gwarp * MAXS;
    float* ds = g_sbuf[pp ^ 1] + gwarp * MAXS;
    const float* fd = g_dfine + gwarp * 16;
    const float* fs = g_sdff  + gwarp * 16;

    if (lane < 16) {
        float v = fd[lane];
        int lo = 0, hi = n;
        while (lo < hi) { int mm = (lo + hi) >> 1; if (d[mm] <= v) lo = mm + 1; else hi = mm; }
        dd[lo + lane] = v;
        ds[lo + lane] = fs[lane];
    }
    for (int a = lane; a < n; a += 32) {
        float v = d[a];
        int lo = 0, hi = 16;
        while (lo < hi) { int mm = (lo + hi) >> 1; if (fd[mm] < v) lo = mm + 1; else hi = mm; }
        dd[a + lo] = v;
        ds[a + lo] = sd[a];
    }
}

// ---------------- final render: warp scans + FFMA2 MLP ----------------------
__global__ void render_kernel(const float* __restrict__ o,
                              const float* __restrict__ sp,
                              const float* __restrict__ w1, const float* __restrict__ b1,
                              const float* __restrict__ w2, const float* __restrict__ b2,
                              float* __restrict__ out) {
    int r = blockIdx.x;
    int tid = threadIdx.x;
    int lane = tid & 31, wid = tid >> 5;
    __shared__ float dsh[128], cdfsh[128], alphash[128];
    __shared__ float w1s[384], b1s[64], w2s[192], b2s[3];
    __shared__ float wtot[4];
    __shared__ float red0[4], red1[4], red2[4];

    for (int i = tid; i < 384; i += 128) w1s[i] = w1[i];
    for (int i = tid; i < 192; i += 128) w2s[i] = w2[i];
    if (tid < 64) b1s[tid] = b1[tid];
    if (tid < 3)  b2s[tid] = b2[tid];

    float s = sp[0];
    float dv = g_dbuf[0][r * MAXS + tid];
    dsh[tid] = dv;
    cdfsh[tid] = sigmoid_precise(g_sbuf[0][r * MAXS + tid] * s);
    __syncthreads();

    float a = 0.0f;
    if (tid < 127)
        a = fmaxf((cdfsh[tid] - cdfsh[tid + 1]) / (cdfsh[tid] + 1e-10f), 0.0f);
    alphash[tid] = a;
    __syncthreads();

    // inclusive product scan of om[tid] = (tid==0)?1:(1-alpha[tid-1]+1e-10)
    float om = (tid == 0) ? 1.0f : (1.0f - alphash[tid - 1] + 1e-10f);
    float p = om;
#pragma unroll
    for (int off = 1; off < 32; off <<= 1) {
        float t = __shfl_up_sync(0xffffffffu, p, off);
        if (lane >= off) p *= t;
    }
    if (lane == 31) wtot[wid] = p;
    __syncthreads();
    float pre = 1.0f;
#pragma unroll
    for (int w = 0; w < 3; w++)
        if (w < wid) pre *= wtot[w];
    float vw = a * (pre * p);

    float rr = 0.f, gg = 0.f, bb = 0.f;
    if (tid < 127) {
        float dm = 0.5f * (dsh[tid] + dsh[tid + 1]);
        float ox = o[r * 3 + 0], oy = o[r * 3 + 1], oz = o[r * 3 + 2];
        float dx = g_dirs[r * 3 + 0], dy = g_dirs[r * 3 + 1], dz = g_dirs[r * 3 + 2];
        float x0 = fmaf(dm, dx, ox), x1 = fmaf(dm, dy, oy), x2 = fmaf(dm, dz, oz);
        u64 X0 = pack2(x0, x0), X1 = pack2(x1, x1), X2 = pack2(x2, x2);
        u64 DX = pack2(dx, dx), DY = pack2(dy, dy), DZ = pack2(dz, dz);
        u64 A0 = 0, A1 = 0, A2 = 0;
#pragma unroll 4
        for (int j = 0; j < 64; j += 2) {
            u64 hp = *(const u64*)&b1s[j];
            hp = ffma2(X0, *(const u64*)&w1s[j],       hp);
            hp = ffma2(X1, *(const u64*)&w1s[64 + j],  hp);
            hp = ffma2(X2, *(const u64*)&w1s[128 + j], hp);
            hp = ffma2(DX, *(const u64*)&w1s[192 + j], hp);
            hp = ffma2(DY, *(const u64*)&w1s[256 + j], hp);
            hp = ffma2(DZ, *(const u64*)&w1s[320 + j], hp);
            float hl, hh;
            unpack2(hp, hl, hh);
            u64 H = pack2(softplus_fast(hl), softplus_fast(hh));
            const float* wr = &w2s[j * 3];
            A0 = ffma2(H, pack2(wr[0], wr[3]), A0);
            A1 = ffma2(H, pack2(wr[1], wr[4]), A1);
            A2 = ffma2(H, pack2(wr[2], wr[5]), A2);
        }
        float l0, h0, l1, h1, l2, h2;
        unpack2(A0, l0, h0);
        unpack2(A1, l1, h1);
        unpack2(A2, l2, h2);
        rr = sigmoid_fast(b2s[0] + l0 + h0) * vw;
        gg = sigmoid_fast(b2s[1] + l1 + h1) * vw;
        bb = sigmoid_fast(b2s[2] + l2 + h2) * vw;
    }
    // warp reduce + cross-warp combine
#pragma unroll
    for (int off = 16; off > 0; off >>= 1) {
        rr += __shfl_xor_sync(0xffffffffu, rr, off);
        gg += __shfl_xor_sync(0xffffffffu, gg, off);
        bb += __shfl_xor_sync(0xffffffffu, bb, off);
    }
    if (lane == 0) { red0[wid] = rr; red1[wid] = gg; red2[wid] = bb; }
    __syncthreads();
    if (tid == 0) out[r * 3 + 0] = red0[0] + red0[1] + red0[2] + red0[3];
    if (tid == 1) out[r * 3 + 1] = red1[0] + red1[1] + red1[2] + red1[3];
    if (tid == 2) out[r * 3 + 2] = red2[0] + red2[1] + red2[2] + red2[3];
}

// ---------------- launch ----------------------------------------------------
extern "C" void kernel_launch(void* const* d_in, const int* in_sizes, int n_in,
                              void* d_out, int out_size) {
    const float* rays_o = (const float*)d_in[0];
    const float* rays_d = (const float*)d_in[1];
    const float* nearp  = (const float*)d_in[2];
    const float* farp   = (const float*)d_in[3];
    const float* s_ptr  = (const float*)d_in[4];
    const float* sw1 = (const float*)d_in[5];
    const float* sb1 = (const float*)d_in[6];
    const float* sw2 = (const float*)d_in[7];
    const float* sb2 = (const float*)d_in[8];
    const float* sw3 = (const float*)d_in[9];
    const float* sb3 = (const float*)d_in[10];
    const float* rw1 = (const float*)d_in[11];
    const float* rb1 = (const float*)d_in[12];
    const float* rw2 = (const float*)d_in[13];
    const float* rb2 = (const float*)d_in[14];
    float* out = (float*)d_out;

    const int sdf_smem = SDF_SMEM_FLOATS * 4;
    cudaFuncSetAttribute(sdf_kernel,
                         cudaFuncAttributeMaxDynamicSharedMemorySize, sdf_smem);

    init_kernel<<<(NRAYS + 255) / 256, 256>>>(rays_d, nearp, farp);

    int cta_coarse = NRAYS * 64 / 128;   // 128 pts per CTA
    sdf_kernel<<<cta_coarse, 256, sdf_smem>>>(
        rays_o, sw1, sb1, sw2, sb2, sw3, sb3, 0);

    int cta_fine = NRAYS * 16 / 128;
    int warps_grid = (NRAYS * 32 + 255) / 256;   // one warp per ray

    // iter 0: upsample from coarse (buffer 0)
    upsample_kernel<<<warps_grid, 256>>>(64, 64.0f, 0);
    sdf_kernel<<<cta_fine, 256, sdf_smem>>>(
        rays_o, sw1, sb1, sw2, sb2, sw3, sb3, 1);

    // iters 1..3: fused merge(prev) + upsample(next)
    int pp = 0;
    for (int i = 1; i < 4; i++) {
        int n_old = 64 + 16 * (i - 1);
        float si = 64.0f * (float)(1 << i);
        fused_merge_upsample<<<warps_grid, 256>>>(n_old, si, pp);
        pp ^= 1;
        sdf_kernel<<<cta_fine, 256, sdf_smem>>>(
            rays_o, sw1, sb1, sw2, sb2, sw3, sb3, 1);
    }

    // final merge: n_old = 112, pp=1 -> buffer 0
    merge_kernel<<<warps_grid, 256>>>(112, pp);

    render_kernel<<<NRAYS, 128>>>(rays_o, s_ptr, rw1, rb1, rw2, rb2, out);
}